// round 12
// baseline (speedup 1.0000x reference)
#include <cuda_runtime.h>
#include <cuda_bf16.h>
#include <math.h>
#include <stdint.h>
#include <string.h>

// ---------------- problem constants ----------------
#define N_PTS   29696
#define N_IN_C  1024
#define E1_C    512
#define E2_C    512
#define E3_C    2048
#define NZ_C    32
#define D1_C    2048
#define D2_C    512
#define D3_C    512
#define K_C     100
#define EPS_C   1e-5f

#define MBLK    (N_PTS / 128)                   // 232
#define MSE_PARTIALS (MBLK * (N_IN_C / 256))    // 928

// z-layer scalar GEMM tiling
#define BM 128
#define BN 64
#define BK 16

// ---------------- scratch ----------------
__device__ float g_bufA[(size_t)N_PTS * 2048];
// component buffer set X
__device__ uint32_t g_cX0[(size_t)N_PTS * 1024];
__device__ uint32_t g_cX1[(size_t)N_PTS * 1024];
__device__ uint32_t g_cX2[(size_t)N_PTS * 512];
// component buffer set Y
__device__ uint32_t g_cY0[(size_t)N_PTS * 1024];
__device__ uint32_t g_cY1[(size_t)N_PTS * 1024];
__device__ uint32_t g_cY2[(size_t)N_PTS * 512];
// weight component buffers
__device__ uint32_t g_cB0[2048 * 1024];
__device__ uint32_t g_cB1[2048 * 1024];
__device__ uint32_t g_cB2[2048 * 1024];
__device__ float g_zbuf[(size_t)N_PTS * NZ_C];
__device__ float g_q[(size_t)K_C * N_PTS];
__device__ int   g_pred[N_PTS];
__device__ float g_Scon[N_PTS];
__device__ float g_u[K_C];
__device__ float g_f[K_C];
__device__ int   g_cnt[K_C];
__device__ float g_S;
__device__ float g_uloss;
__device__ float g_msep[MSE_PARTIALS];
__device__ float g_klp[MBLK];

__global__ void init_kernel() {
    int t = threadIdx.x;
    if (t < K_C) g_cnt[t] = 0;
}

// ---------------- helpers ----------------
__device__ __forceinline__ uint16_t bf16b(float x) {
    __nv_bfloat16 h = __float2bfloat16_rn(x);
    return *reinterpret_cast<uint16_t*>(&h);
}
__device__ __forceinline__ float bf2f(uint16_t b) {
    __nv_bfloat16 h;
    memcpy(&h, &b, 2);
    return __bfloat162float(h);
}
__device__ __forceinline__ void mma16(float* d, const uint32_t* a, const uint32_t* b) {
    asm volatile(
        "mma.sync.aligned.m16n8k16.row.col.f32.bf16.bf16.f32 "
        "{%0,%1,%2,%3}, {%4,%5,%6,%7}, {%8,%9}, {%0,%1,%2,%3};"
        : "+f"(d[0]), "+f"(d[1]), "+f"(d[2]), "+f"(d[3])
        : "r"(a[0]), "r"(a[1]), "r"(a[2]), "r"(a[3]), "r"(b[0]), "r"(b[1]));
}
__device__ __forceinline__ void cpa16(uint32_t dst_smem, const void* src) {
    asm volatile("cp.async.cg.shared.global [%0], [%1], 16;"
                 :: "r"(dst_smem), "l"(__cvta_generic_to_global(src)));
}

// ---------------- split kernels (standalone: used for x and z only) ----------------
template <int NSPLIT>
__global__ void splitA_bf(const float* __restrict__ src,
                          uint32_t* __restrict__ c0, uint32_t* __restrict__ c1,
                          uint32_t* __restrict__ c2,
                          int MK2, int logK) {
    int idx = blockIdx.x * 256 + threadIdx.x;
    if (idx >= MK2) return;
    const int K2 = 1 << (logK - 1);
    int k2 = idx & (K2 - 1);
    int m = idx >> (logK - 1);
    int k = k2 << 1;
    float v0 = src[((size_t)m << logK) + k];
    float v1 = src[((size_t)m << logK) + k + 1];
    uint16_t a0[3], a1[3];
    float r = v0;
#pragma unroll
    for (int c = 0; c < NSPLIT; c++) { uint16_t b = bf16b(r); a0[c] = b; r -= bf2f(b); }
    r = v1;
#pragma unroll
    for (int c = 0; c < NSPLIT; c++) { uint16_t b = bf16b(r); a1[c] = b; r -= bf2f(b); }
    const int Ktiles = 1 << (logK - 4);
    int klo = k & 15;
    int tile = (m >> 4) * Ktiles + (k >> 4);
    int lane = (m & 7) * 4 + ((klo & 7) >> 1);
    int slot = ((m >> 3) & 1) + ((klo >> 3) << 1);
    size_t off = (size_t)tile * 128 + lane * 4 + slot;
    c0[off] = (uint32_t)a0[0] | ((uint32_t)a1[0] << 16);
    if (NSPLIT >= 2) c1[off] = (uint32_t)a0[1] | ((uint32_t)a1[1] << 16);
    if (NSPLIT >= 3) c2[off] = (uint32_t)a0[2] | ((uint32_t)a1[2] << 16);
}

template <int NSPLIT>
__global__ void splitB_bf(const float* __restrict__ W,
                          uint32_t* __restrict__ c0, uint32_t* __restrict__ c1,
                          uint32_t* __restrict__ c2,
                          int KN2, int logN, int K) {
    int idx = blockIdx.x * 256 + threadIdx.x;
    if (idx >= KN2) return;
    int n = idx & ((1 << logN) - 1);
    int k2 = idx >> logN;
    int k = k2 << 1;
    float v0 = W[((size_t)k << logN) + n];
    float v1 = W[((size_t)(k + 1) << logN) + n];
    uint16_t a0[3], a1[3];
    float r = v0;
#pragma unroll
    for (int c = 0; c < NSPLIT; c++) { uint16_t b = bf16b(r); a0[c] = b; r -= bf2f(b); }
    r = v1;
#pragma unroll
    for (int c = 0; c < NSPLIT; c++) { uint16_t b = bf16b(r); a1[c] = b; r -= bf2f(b); }
    const int Ktiles = K >> 4;
    int klo = k & 15;
    int tile = (n >> 3) * Ktiles + (k >> 4);
    int lane = (n & 7) * 4 + ((klo & 7) >> 1);
    int slot = klo >> 3;
    size_t off = (size_t)tile * 64 + lane * 2 + slot;
    c0[off] = (uint32_t)a0[0] | ((uint32_t)a1[0] << 16);
    if (NSPLIT >= 2) c1[off] = (uint32_t)a0[1] | ((uint32_t)a1[1] << 16);
    if (NSPLIT >= 3) c2[off] = (uint32_t)a0[2] | ((uint32_t)a1[2] << 16);
}

// ---------------- 2-stage pipelined split-bf16 mma GEMM, 512 threads (R10-proven core) ----------------
// Block tile 128x256, K-chunk 32. 16 warps (2x8), warp tile 64x32.
// MODE 0: C = relu(.)+bias -> fp32 C. MODE 1: MSE vs Xref. MODE 2: relu+bias -> OSPLIT bf16 comps (fused split).
template <int NSPLIT, int MODE, int OSPLIT>
__global__ void __launch_bounds__(512, 1) mma_bf(
    const uint32_t* __restrict__ A0, const uint32_t* __restrict__ A1,
    const uint32_t* __restrict__ A2,
    const uint32_t* __restrict__ B0, const uint32_t* __restrict__ B1,
    const uint32_t* __restrict__ B2,
    const float* __restrict__ bias, float* __restrict__ C,
    const float* __restrict__ Xref, float* __restrict__ partial,
    uint32_t* __restrict__ O0, uint32_t* __restrict__ O1, uint32_t* __restrict__ O2,
    int K, int N)
{
    extern __shared__ uint32_t smu[];
    const int STAGE_U = NSPLIT * 6144;
    const int tid = threadIdx.x;
    const int wid = tid >> 5;
    const int lane = tid & 31;
    const int warpM = wid >> 3;          // 0..1
    const int warpN = wid & 7;           // 0..7
    const int rowBlock = blockIdx.y * 128;
    const int colBlock = blockIdx.x * 256;
    const int rowTile = blockIdx.y * 8;
    const int colTile = blockIdx.x * 32;
    const int Ktiles = K >> 4;
    const int nch = K >> 5;

    const uint32_t* Ac[3] = { A0, A1, A2 };
    const uint32_t* Bc[3] = { B0, B1, B2 };
    const uint32_t smem_base = (uint32_t)__cvta_generic_to_shared(smu);

    constexpr int NT = (NSPLIT == 3) ? 6 : 3;
    constexpr int TA3[6] = {0, 2, 1, 0, 1, 0};
    constexpr int TB3[6] = {2, 0, 1, 1, 0, 0};
    constexpr int TA2[3] = {1, 0, 0};
    constexpr int TB2[3] = {0, 1, 0};

    float d[4][4][4];
#pragma unroll
    for (int mt = 0; mt < 4; mt++)
#pragma unroll
        for (int nt = 0; nt < 4; nt++)
#pragma unroll
            for (int i = 0; i < 4; i++) d[mt][nt][i] = 0.f;

    auto copy_stage = [&](int s, int c) {
        const uint32_t sb = smem_base + (uint32_t)(s * STAGE_U) * 4u;
#pragma unroll
        for (int j = 0; j < NSPLIT; j++) {
            int o = j * 512 + tid;
            int comp = o >> 9;
            int rem = o & 511;
            int mt = rem >> 6;
            int w = (rem & 63) * 4;
            cpa16(sb + (uint32_t)(comp * 2048 + mt * 256 + w) * 4u,
                  Ac[comp] + ((size_t)(rowTile + mt) * Ktiles + 2 * c) * 128 + w);
        }
#pragma unroll
        for (int j = 0; j < NSPLIT * 2; j++) {
            int o = j * 512 + tid;
            int comp = o >> 10;
            int rem = o & 1023;
            int nt = rem >> 5;
            int w = (rem & 31) * 4;
            cpa16(sb + (uint32_t)(NSPLIT * 2048 + comp * 4096 + nt * 128 + w) * 4u,
                  Bc[comp] + ((size_t)(colTile + nt) * Ktiles + 2 * c) * 64 + w);
        }
    };

    auto compute_stage = [&](int s) {
        const uint32_t* sA = smu + s * STAGE_U;
        const uint32_t* sB = sA + NSPLIT * 2048;
#pragma unroll
        for (int ks = 0; ks < 2; ks++) {
            uint32_t bf[NSPLIT][4][2];
#pragma unroll
            for (int nt = 0; nt < 4; nt++)
#pragma unroll
                for (int cc = 0; cc < NSPLIT; cc++) {
                    const uint32_t* p = &sB[cc * 4096 + (warpN * 4 + nt) * 128 + ks * 64 + lane * 2];
                    bf[cc][nt][0] = p[0];
                    bf[cc][nt][1] = p[1];
                }
#pragma unroll
            for (int mt = 0; mt < 4; mt++) {
                uint32_t af[NSPLIT][4];
#pragma unroll
                for (int cc = 0; cc < NSPLIT; cc++) {
                    const uint32_t* p = &sA[cc * 2048 + (warpM * 4 + mt) * 256 + ks * 128 + lane * 4];
                    af[cc][0] = p[0]; af[cc][1] = p[1]; af[cc][2] = p[2]; af[cc][3] = p[3];
                }
#pragma unroll
                for (int nt = 0; nt < 4; nt++) {
#pragma unroll
                    for (int t = 0; t < NT; t++) {
                        int ta = (NSPLIT == 3) ? TA3[t] : TA2[t];
                        int tb = (NSPLIT == 3) ? TB3[t] : TB2[t];
                        mma16(d[mt][nt], af[ta], bf[tb][nt]);
                    }
                }
            }
        }
    };

    // prologue: 2 stages (R10-proven)
    const int pre = (nch < 2) ? nch : 2;
    for (int s = 0; s < pre; s++) {
        copy_stage(s, s);
        asm volatile("cp.async.commit_group;" ::: "memory");
    }
    for (int c = 0; c < nch; c++) {
        if (c < nch - 1) asm volatile("cp.async.wait_group 1;" ::: "memory");
        else             asm volatile("cp.async.wait_group 0;" ::: "memory");
        __syncthreads();
        compute_stage(c & 1);
        if (c + 2 < nch) {
            __syncthreads();
            copy_stage(c & 1, c + 2);
            asm volatile("cp.async.commit_group;" ::: "memory");
        }
    }

    // ---- epilogue ----
    float2 bb[4];
#pragma unroll
    for (int nt = 0; nt < 4; nt++)
        bb[nt] = *reinterpret_cast<const float2*>(
            &bias[colBlock + warpN * 32 + nt * 8 + (lane & 3) * 2]);

    if (MODE == 0) {
#pragma unroll
        for (int mt = 0; mt < 4; mt++) {
            const int r0 = rowBlock + warpM * 64 + mt * 16 + (lane >> 2);
#pragma unroll
            for (int nt = 0; nt < 4; nt++) {
                const int col = colBlock + warpN * 32 + nt * 8 + (lane & 3) * 2;
                float2 v0, v1;
                v0.x = fmaxf(d[mt][nt][0] + bb[nt].x, 0.f);
                v0.y = fmaxf(d[mt][nt][1] + bb[nt].y, 0.f);
                v1.x = fmaxf(d[mt][nt][2] + bb[nt].x, 0.f);
                v1.y = fmaxf(d[mt][nt][3] + bb[nt].y, 0.f);
                *reinterpret_cast<float2*>(&C[(size_t)r0 * N + col]) = v0;
                *reinterpret_cast<float2*>(&C[(size_t)(r0 + 8) * N + col]) = v1;
            }
        }
    } else if (MODE == 2) {
        // fused bias+relu+split -> fragment-major component buffers (next layer's A, K=N)
        const int Kt = N >> 4;
#pragma unroll
        for (int mt = 0; mt < 4; mt++) {
            const int r0 = rowBlock + warpM * 64 + mt * 16 + (lane >> 2);
#pragma unroll
            for (int nt = 0; nt < 4; nt++) {
                const int col = colBlock + warpN * 32 + nt * 8 + (lane & 3) * 2;
#pragma unroll
                for (int half = 0; half < 2; half++) {
                    const int r = r0 + half * 8;
                    float rx = fmaxf(d[mt][nt][half * 2 + 0] + bb[nt].x, 0.f);
                    float ry = fmaxf(d[mt][nt][half * 2 + 1] + bb[nt].y, 0.f);
                    const int tile = (r >> 4) * Kt + (col >> 4);
                    const int lanei = (r & 7) * 4 + ((col & 7) >> 1);
                    const int slot = ((r >> 3) & 1) + (((col & 15) >> 3) << 1);
                    const size_t off = (size_t)tile * 128 + lanei * 4 + slot;
#pragma unroll
                    for (int cc = 0; cc < OSPLIT; cc++) {
                        uint16_t bx = bf16b(rx); rx -= bf2f(bx);
                        uint16_t by = bf16b(ry); ry -= bf2f(by);
                        uint32_t pv = (uint32_t)bx | ((uint32_t)by << 16);
                        if (cc == 0) O0[off] = pv;
                        else if (cc == 1) O1[off] = pv;
                        else O2[off] = pv;
                    }
                }
            }
        }
    } else {
        float msum = 0.f;
#pragma unroll
        for (int mt = 0; mt < 4; mt++) {
            const int r0 = rowBlock + warpM * 64 + mt * 16 + (lane >> 2);
#pragma unroll
            for (int nt = 0; nt < 4; nt++) {
                const int col = colBlock + warpN * 32 + nt * 8 + (lane & 3) * 2;
                float2 x0 = *reinterpret_cast<const float2*>(&Xref[(size_t)r0 * N + col]);
                float2 x1 = *reinterpret_cast<const float2*>(&Xref[(size_t)(r0 + 8) * N + col]);
                float e;
                e = d[mt][nt][0] + bb[nt].x - x0.x; msum = fmaf(e, e, msum);
                e = d[mt][nt][1] + bb[nt].y - x0.y; msum = fmaf(e, e, msum);
                e = d[mt][nt][2] + bb[nt].x - x1.x; msum = fmaf(e, e, msum);
                e = d[mt][nt][3] + bb[nt].y - x1.y; msum = fmaf(e, e, msum);
            }
        }
        __syncthreads();
        float* red = reinterpret_cast<float*>(smu);
        red[tid] = msum;
        __syncthreads();
        for (int o = 256; o > 0; o >>= 1) {
            if (tid < o) red[tid] += red[tid + o];
            __syncthreads();
        }
        if (tid == 0) partial[blockIdx.y * gridDim.x + blockIdx.x] = red[0];
    }
}

// ---------------- small-N fp32 scalar GEMM (z layer, N=32) ----------------
__global__ __launch_bounds__(256) void gemm_relu(
    const float* __restrict__ A, const float* __restrict__ W,
    const float* __restrict__ bias, float* __restrict__ C,
    int M, int K, int N, int doRelu)
{
    __shared__ float As[BK][BM];
    __shared__ float Wsm[BK][BN];
    const int tid = threadIdx.x;
    const int rowBlock = blockIdx.y * BM;
    const int colBlock = blockIdx.x * BN;
    const int tx = tid & 15;
    const int ty = tid >> 4;
    const int rBase = ty * 8;
    const int cBase = tx * 4;

    float acc[8][4];
#pragma unroll
    for (int i = 0; i < 8; i++)
#pragma unroll
        for (int j = 0; j < 4; j++) acc[i][j] = 0.f;

    const int aRow0 = tid >> 2;
    const int aF4   = tid & 3;
    const int wK    = tid >> 4;
    const int wC    = (tid & 15) * 4;

    for (int k0 = 0; k0 < K; k0 += BK) {
#pragma unroll
        for (int h = 0; h < 2; h++) {
            int r = aRow0 + h * 64;
            float4 v = *reinterpret_cast<const float4*>(
                &A[(size_t)(rowBlock + r) * K + k0 + aF4 * 4]);
            As[aF4 * 4 + 0][r] = v.x;
            As[aF4 * 4 + 1][r] = v.y;
            As[aF4 * 4 + 2][r] = v.z;
            As[aF4 * 4 + 3][r] = v.w;
        }
        {
            int col = colBlock + wC;
            float4 v = make_float4(0.f, 0.f, 0.f, 0.f);
            if (col + 3 < N) {
                v = *reinterpret_cast<const float4*>(&W[(size_t)(k0 + wK) * N + col]);
            } else {
                float tmp[4] = {0.f, 0.f, 0.f, 0.f};
                for (int j = 0; j < 4; j++)
                    if (col + j < N) tmp[j] = W[(size_t)(k0 + wK) * N + col + j];
                v = make_float4(tmp[0], tmp[1], tmp[2], tmp[3]);
            }
            *reinterpret_cast<float4*>(&Wsm[wK][wC]) = v;
        }
        __syncthreads();
#pragma unroll
        for (int kk = 0; kk < BK; kk++) {
            float a[8], b[4];
#pragma unroll
            for (int i = 0; i < 8; i++) a[i] = As[kk][rBase + i];
#pragma unroll
            for (int j = 0; j < 4; j++) b[j] = Wsm[kk][cBase + j];
#pragma unroll
            for (int i = 0; i < 8; i++)
#pragma unroll
                for (int j = 0; j < 4; j++) acc[i][j] = fmaf(a[i], b[j], acc[i][j]);
        }
        __syncthreads();
    }
#pragma unroll
    for (int i = 0; i < 8; i++) {
        int row = rowBlock + rBase + i;
#pragma unroll
        for (int j = 0; j < 4; j++) {
            int col = colBlock + cBase + j;
            if (col < N) {
                float v = acc[i][j] + bias[col];
                if (doRelu) v = fmaxf(v, 0.f);
                C[(size_t)row * N + col] = v;
            }
        }
    }
}

// ---------------- pass A ----------------
__global__ __launch_bounds__(128) void passA(
    const float* __restrict__ z, const float* __restrict__ t1,
    const float* __restrict__ clus, float* __restrict__ q,
    int* __restrict__ pred, float* __restrict__ scon,
    float* __restrict__ out, int out_size)
{
    __shared__ float cs[K_C * NZ_C];
    const int tid = threadIdx.x;
    for (int i = tid; i < K_C * NZ_C; i += 128) cs[i] = clus[i];
    __syncthreads();

    const int n = blockIdx.x * 128 + tid;
    if (n >= N_PTS) return;

    const float tx = t1[n * 3 + 0] * 0.01f;
    const float ty = t1[n * 3 + 1] * 0.01f;
    const float tz = t1[n * 3 + 2] * 0.01f;
    const float cm = tx * ty * tz * 0.99f + 1.0f;

    float zp[NZ_C];
    const float* zr = &z[(size_t)n * NZ_C];
    float mean = 0.f;
#pragma unroll
    for (int i = 0; i < NZ_C; i++) { zp[i] = zr[i] * cm; mean += zp[i]; }
    mean *= (1.0f / NZ_C);
    float var = 0.f;
#pragma unroll
    for (int i = 0; i < NZ_C; i++) { float dd = zp[i] - mean; var += dd * dd; }
    var *= (1.0f / (NZ_C - 1));
    const float invstd = 1.0f / sqrtf(var);
#pragma unroll
    for (int i = 0; i < NZ_C; i++) zp[i] = (zp[i] - mean) * invstd;

    float qsum = 0.f;
    float best = -1.f;
    int bestk = 0;
    for (int k = 0; k < K_C; k++) {
        const float* c = &cs[k * NZ_C];
        float dsum = 0.f;
#pragma unroll
        for (int i = 0; i < NZ_C; i++) { float df = zp[i] - c[i]; dsum = fmaf(df, df, dsum); }
        float qr = EPS_C + dsum;
        q[(size_t)k * N_PTS + n] = qr;
        qsum += qr;
        if (qr > best) { best = qr; bestk = k; }
    }
    const float inv = 1.0f / qsum;
    float s = 0.f;
    for (int k = 0; k < K_C; k++) {
        float qn = q[(size_t)k * N_PTS + n] * inv;
        q[(size_t)k * N_PTS + n] = qn;
        float l = logf(qn);
        float t = 1.0f - qn;
        float neg_temp = t * t * (-l) * (float)N_PTS;
        s += 1.0f / sqrtf(neg_temp);
    }
    pred[n] = bestk;
    scon[n] = s;
    if (n < out_size) out[n] = (float)bestk;
    atomicAdd(&g_cnt[bestk], 1);
}

// ---------------- reductions ----------------
__global__ void ureduce(const float* __restrict__ q) {
    __shared__ float sh[256];
    const int k = blockIdx.x;
    float s = 0.f;
    for (int n = threadIdx.x; n < N_PTS; n += 256) s += q[(size_t)k * N_PTS + n];
    sh[threadIdx.x] = s;
    __syncthreads();
    for (int o = 128; o > 0; o >>= 1) {
        if (threadIdx.x < o) sh[threadIdx.x] += sh[threadIdx.x + o];
        __syncthreads();
    }
    if (threadIdx.x == 0) g_u[k] = sh[0];
}

__global__ void sreduce(const float* __restrict__ scon) {
    __shared__ float sh[256];
    float s = 0.f;
    for (int n = threadIdx.x; n < N_PTS; n += 256) s += scon[n];
    sh[threadIdx.x] = s;
    __syncthreads();
    for (int o = 128; o > 0; o >>= 1) {
        if (threadIdx.x < o) sh[threadIdx.x] += sh[threadIdx.x + o];
        __syncthreads();
    }
    if (threadIdx.x == 0) g_S = sh[0];
}

__global__ void passB(const float* __restrict__ clus) {
    __shared__ float sh[256];
    const int tid = threadIdx.x;
    float s = 0.f;
    for (int p = tid; p < K_C * K_C; p += 256) {
        int i = p / K_C, j = p - i * K_C;
        const float* a = &clus[i * NZ_C];
        const float* b = &clus[j * NZ_C];
        float dsum = 0.f;
#pragma unroll
        for (int t = 0; t < NZ_C; t++) { float df = a[t] - b[t]; dsum = fmaf(df, df, dsum); }
        s += dsum;
    }
    sh[tid] = s;
    __syncthreads();
    for (int o = 128; o > 0; o >>= 1) {
        if (tid < o) sh[tid] += sh[tid + o];
        __syncthreads();
    }
    if (tid == 0) {
        float md = sh[0] / (float)(K_C * K_C - K_C);
        g_uloss = 0.01f / md;

        float un[K_C], vn[K_C];
        float um = 0.f;
        for (int k = 0; k < K_C; k++) um += g_u[k];
        um /= (float)K_C;
        float uv = 0.f;
        for (int k = 0; k < K_C; k++) { float dd = g_u[k] - um; uv += dd * dd; }
        uv /= (float)(K_C - 1);
        float uis = 1.0f / sqrtf(uv);
        for (int k = 0; k < K_C; k++) un[k] = (g_u[k] - um) * uis;

        float S = g_S;
        float vm = 0.f;
        for (int k = 0; k < K_C; k++) {
            float nc = (g_cnt[k] > 0) ? (float)g_cnt[k] : 1.0f;
            vn[k] = sqrtf(nc) * S;
            vm += vn[k];
        }
        vm /= (float)K_C;
        float vv = 0.f;
        for (int k = 0; k < K_C; k++) { float dd = vn[k] - vm; vv += dd * dd; }
        vv /= (float)(K_C - 1);
        float vis = 1.0f / sqrtf(vv);
        for (int k = 0; k < K_C; k++) vn[k] = (vn[k] - vm) * vis;

        float umin = un[0], vmin = vn[0];
        for (int k = 1; k < K_C; k++) {
            umin = fminf(umin, un[k]);
            vmin = fminf(vmin, vn[k]);
        }
        for (int k = 0; k < K_C; k++) {
            g_f[k] = (un[k] - umin + 0.001f) + (vn[k] - vmin + 0.001f) + 1.0f;
        }
    }
}

__global__ __launch_bounds__(128) void passC(const float* __restrict__ q,
                                             float* __restrict__ klp) {
    __shared__ float fsh[K_C];
    __shared__ float sh[128];
    const int tid = threadIdx.x;
    for (int i = tid; i < K_C; i += 128) fsh[i] = g_f[i];
    __syncthreads();
    const int n = blockIdx.x * 128 + tid;
    float kl = 0.f;
    float ws = 0.f;
    for (int k = 0; k < K_C; k++) {
        float qv = q[(size_t)k * N_PTS + n];
        ws += qv * qv / fsh[k];
    }
    float inv = 1.0f / ws;
    for (int k = 0; k < K_C; k++) {
        float qv = q[(size_t)k * N_PTS + n];
        float p = qv * qv / fsh[k] * inv;
        kl += p * (logf(p) - logf(qv));
    }
    sh[tid] = kl;
    __syncthreads();
    for (int o = 64; o > 0; o >>= 1) {
        if (tid < o) sh[tid] += sh[tid + o];
        __syncthreads();
    }
    if (tid == 0) klp[blockIdx.x] = sh[0];
}

__global__ void finalk(float* __restrict__ out, int out_size) {
    __shared__ float sh[256];
    __shared__ float tot[2];
    const int tid = threadIdx.x;
    float s = 0.f;
    for (int i = tid; i < MSE_PARTIALS; i += 256) s += g_msep[i];
    sh[tid] = s;
    __syncthreads();
    for (int o = 128; o > 0; o >>= 1) {
        if (tid < o) sh[tid] += sh[tid + o];
        __syncthreads();
    }
    if (tid == 0) tot[0] = sh[0];
    __syncthreads();
    s = 0.f;
    for (int i = tid; i < MBLK; i += 256) s += g_klp[i];
    sh[tid] = s;
    __syncthreads();
    for (int o = 128; o > 0; o >>= 1) {
        if (tid < o) sh[tid] += sh[tid + o];
        __syncthreads();
    }
    if (tid == 0) tot[1] = sh[0];
    __syncthreads();
    if (tid == 0) {
        float re_loss = tot[0] / ((float)N_PTS * (float)N_IN_C);
        float kl_loss = tot[1] / ((float)N_PTS * (float)K_C) * 0.01f;
        float loss = kl_loss + re_loss + g_uloss;
        if (out_size > N_PTS) out[N_PTS] = loss;
    }
}

// ---------------- launch ----------------
extern "C" void kernel_launch(void* const* d_in, const int* in_sizes, int n_in,
                              void* d_out, int out_size) {
    const float* x    = (const float*)d_in[0];
    const float* t1   = (const float*)d_in[1];
    const float* clus = (const float*)d_in[2];
    const float* We1  = (const float*)d_in[3];
    const float* be1  = (const float*)d_in[4];
    const float* We2  = (const float*)d_in[5];
    const float* be2  = (const float*)d_in[6];
    const float* We3  = (const float*)d_in[7];
    const float* be3  = (const float*)d_in[8];
    const float* Wz   = (const float*)d_in[9];
    const float* bz   = (const float*)d_in[10];
    const float* Wd1  = (const float*)d_in[11];
    const float* bd1  = (const float*)d_in[12];
    const float* Wd2  = (const float*)d_in[13];
    const float* bd2  = (const float*)d_in[14];
    const float* Wd3  = (const float*)d_in[15];
    const float* bd3  = (const float*)d_in[16];
    const float* Wxb  = (const float*)d_in[17];
    const float* bxb  = (const float*)d_in[18];
    float* out = (float*)d_out;

    float *bufA, *zbuf, *qbuf, *scon, *msep, *klp;
    uint32_t *cX0, *cX1, *cX2, *cY0, *cY1, *cY2, *cB0, *cB1, *cB2;
    int *pred;
    cudaGetSymbolAddress((void**)&bufA, g_bufA);
    cudaGetSymbolAddress((void**)&cX0, g_cX0);
    cudaGetSymbolAddress((void**)&cX1, g_cX1);
    cudaGetSymbolAddress((void**)&cX2, g_cX2);
    cudaGetSymbolAddress((void**)&cY0, g_cY0);
    cudaGetSymbolAddress((void**)&cY1, g_cY1);
    cudaGetSymbolAddress((void**)&cY2, g_cY2);
    cudaGetSymbolAddress((void**)&cB0, g_cB0);
    cudaGetSymbolAddress((void**)&cB1, g_cB1);
    cudaGetSymbolAddress((void**)&cB2, g_cB2);
    cudaGetSymbolAddress((void**)&zbuf, g_zbuf);
    cudaGetSymbolAddress((void**)&qbuf, g_q);
    cudaGetSymbolAddress((void**)&pred, g_pred);
    cudaGetSymbolAddress((void**)&scon, g_Scon);
    cudaGetSymbolAddress((void**)&msep, g_msep);
    cudaGetSymbolAddress((void**)&klp,  g_klp);

    const int DS3 = 2 * 3 * 6144 * 4;   // 147456 B
    const int DS2 = 2 * 2 * 6144 * 4;   //  98304 B
    cudaFuncSetAttribute(mma_bf<3, 2, 3>, cudaFuncAttributeMaxDynamicSharedMemorySize, DS3);
    cudaFuncSetAttribute(mma_bf<3, 0, 0>, cudaFuncAttributeMaxDynamicSharedMemorySize, DS3);
    cudaFuncSetAttribute(mma_bf<2, 2, 2>, cudaFuncAttributeMaxDynamicSharedMemorySize, DS2);
    cudaFuncSetAttribute(mma_bf<2, 1, 0>, cudaFuncAttributeMaxDynamicSharedMemorySize, DS2);

    init_kernel<<<1, 128>>>();
    auto nb = [](int elems) { return (elems + 255) / 256; };

    // ---- encoder: 3-way bf16 split, 6 terms; fused split epilogues ----
    splitA_bf<3><<<nb(N_PTS * 512), 256>>>(x, cX0, cX1, cX2, N_PTS * 512, 10);
    splitB_bf<3><<<nb(512 * E1_C), 256>>>(We1, cB0, cB1, cB2, 512 * E1_C, 9, N_IN_C);
    mma_bf<3, 2, 3><<<dim3(E1_C / 256, MBLK), 512, DS3>>>(cX0, cX1, cX2, cB0, cB1, cB2,
        be1, nullptr, nullptr, nullptr, cY0, cY1, cY2, N_IN_C, E1_C);

    splitB_bf<3><<<nb(256 * E2_C), 256>>>(We2, cB0, cB1, cB2, 256 * E2_C, 9, E1_C);
    mma_bf<3, 2, 3><<<dim3(E2_C / 256, MBLK), 512, DS3>>>(cY0, cY1, cY2, cB0, cB1, cB2,
        be2, nullptr, nullptr, nullptr, cX0, cX1, cX2, E1_C, E2_C);

    splitB_bf<3><<<nb(256 * E3_C), 256>>>(We3, cB0, cB1, cB2, 256 * E3_C, 11, E2_C);
    mma_bf<3, 0, 0><<<dim3(E3_C / 256, MBLK), 512, DS3>>>(cX0, cX1, cX2, cB0, cB1, cB2,
        be3, bufA, nullptr, nullptr, nullptr, nullptr, nullptr, E2_C, E3_C);

    // z layer (scalar fp32, N=32) then split z
    gemm_relu<<<dim3(1, N_PTS / BM), 256>>>(bufA, Wz, bz, zbuf, N_PTS, E3_C, NZ_C, 0);
    splitA_bf<2><<<nb(N_PTS * 16), 256>>>(zbuf, cX0, cX1, nullptr, N_PTS * 16, 5);

    // ---- decoder: 2-way bf16 split, 3 terms; fused split epilogues ----
    splitB_bf<2><<<nb(16 * D1_C), 256>>>(Wd1, cB0, cB1, nullptr, 16 * D1_C, 11, NZ_C);
    mma_bf<2, 2, 2><<<dim3(D1_C / 256, MBLK), 512, DS2>>>(cX0, cX1, nullptr, cB0, cB1, nullptr,
        bd1, nullptr, nullptr, nullptr, cY0, cY1, nullptr, NZ_C, D1_C);

    splitB_bf<2><<<nb(1024 * D2_C), 256>>>(Wd2, cB0, cB1, nullptr, 1024 * D2_C, 9, D1_C);
    mma_bf<2, 2, 2><<<dim3(D2_C / 256, MBLK), 512, DS2>>>(cY0, cY1, nullptr, cB0, cB1, nullptr,
        bd2, nullptr, nullptr, nullptr, cX0, cX1, nullptr, D1_C, D2_C);

    splitB_bf<2><<<nb(256 * D3_C), 256>>>(Wd3, cB0, cB1, nullptr, 256 * D3_C, 9, D2_C);
    mma_bf<2, 2, 2><<<dim3(D3_C / 256, MBLK), 512, DS2>>>(cX0, cX1, nullptr, cB0, cB1, nullptr,
        bd3, nullptr, nullptr, nullptr, cY0, cY1, nullptr, D2_C, D3_C);

    splitB_bf<2><<<nb(256 * N_IN_C), 256>>>(Wxb, cB0, cB1, nullptr, 256 * N_IN_C, 10, D3_C);
    mma_bf<2, 1, 0><<<dim3(N_IN_C / 256, MBLK), 512, DS2>>>(cY0, cY1, nullptr, cB0, cB1, nullptr,
        bxb, nullptr, x, msep, nullptr, nullptr, nullptr, D3_C, N_IN_C);

    // ---- clustering + losses ----
    passA<<<MBLK, 128>>>(zbuf, t1, clus, qbuf, pred, scon, out, out_size);
    ureduce<<<K_C, 256>>>(qbuf);
    sreduce<<<1, 256>>>(scon);
    passB<<<1, 256>>>(clus);
    passC<<<MBLK, 128>>>(qbuf, klp);
    finalk<<<1, 256>>>(out, out_size);
}

// round 13
// speedup vs baseline: 1.5211x; 1.5211x over previous
#include <cuda_runtime.h>
#include <cuda_bf16.h>
#include <math.h>
#include <stdint.h>
#include <string.h>

// ---------------- problem constants ----------------
#define N_PTS   29696
#define N_IN_C  1024
#define E1_C    512
#define E2_C    512
#define E3_C    2048
#define NZ_C    32
#define D1_C    2048
#define D2_C    512
#define D3_C    512
#define K_C     100
#define EPS_C   1e-5f

#define MBLK    (N_PTS / 128)                   // 232
#define MSE_PARTIALS (MBLK * (N_IN_C / 256))    // 928

// z-layer scalar GEMM tiling
#define BM 128
#define BN 64
#define BK 16

// ---------------- scratch ----------------
__device__ float g_bufA[(size_t)N_PTS * 2048];
__device__ float g_bufB[(size_t)N_PTS * 2048];
// bf16-pair component buffers (u32 = 2 packed bf16), fragment-major layouts
__device__ uint32_t g_cA0[(size_t)N_PTS * 1024];
__device__ uint32_t g_cA1[(size_t)N_PTS * 1024];
__device__ uint32_t g_cA2[(size_t)N_PTS * 512];
__device__ uint32_t g_cB0[2048 * 1024];
__device__ uint32_t g_cB1[2048 * 1024];
__device__ uint32_t g_cB2[2048 * 1024];
__device__ float g_zbuf[(size_t)N_PTS * NZ_C];
__device__ float g_q[(size_t)K_C * N_PTS];
__device__ int   g_pred[N_PTS];
__device__ float g_Scon[N_PTS];
__device__ float g_u[K_C];
__device__ float g_f[K_C];
__device__ int   g_cnt[K_C];
__device__ float g_S;
__device__ float g_uloss;
__device__ float g_msep[MSE_PARTIALS];
__device__ float g_klp[MBLK];

__global__ void init_kernel() {
    int t = threadIdx.x;
    if (t < K_C) g_cnt[t] = 0;
}

// ---------------- helpers ----------------
__device__ __forceinline__ uint16_t bf16b(float x) {
    __nv_bfloat16 h = __float2bfloat16_rn(x);
    return *reinterpret_cast<uint16_t*>(&h);
}
__device__ __forceinline__ float bf2f(uint16_t b) {
    __nv_bfloat16 h;
    memcpy(&h, &b, 2);
    return __bfloat162float(h);
}
__device__ __forceinline__ void mma16(float* d, const uint32_t* a, const uint32_t* b) {
    asm volatile(
        "mma.sync.aligned.m16n8k16.row.col.f32.bf16.bf16.f32 "
        "{%0,%1,%2,%3}, {%4,%5,%6,%7}, {%8,%9}, {%0,%1,%2,%3};"
        : "+f"(d[0]), "+f"(d[1]), "+f"(d[2]), "+f"(d[3])
        : "r"(a[0]), "r"(a[1]), "r"(a[2]), "r"(a[3]), "r"(b[0]), "r"(b[1]));
}
__device__ __forceinline__ void cpa16(uint32_t dst_smem, const void* src) {
    asm volatile("cp.async.cg.shared.global [%0], [%1], 16;"
                 :: "r"(dst_smem), "l"(__cvta_generic_to_global(src)));
}

// ---------------- split kernels (fp32 -> NSPLIT bf16 components, fragment-major) ----------------
template <int NSPLIT>
__global__ void splitA_bf(const float* __restrict__ src,
                          uint32_t* __restrict__ c0, uint32_t* __restrict__ c1,
                          uint32_t* __restrict__ c2,
                          int MK2, int logK) {
    int idx = blockIdx.x * 256 + threadIdx.x;
    if (idx >= MK2) return;
    const int K2 = 1 << (logK - 1);
    int k2 = idx & (K2 - 1);
    int m = idx >> (logK - 1);
    int k = k2 << 1;
    float v0 = src[((size_t)m << logK) + k];
    float v1 = src[((size_t)m << logK) + k + 1];
    uint16_t a0[3], a1[3];
    float r = v0;
#pragma unroll
    for (int c = 0; c < NSPLIT; c++) { uint16_t b = bf16b(r); a0[c] = b; r -= bf2f(b); }
    r = v1;
#pragma unroll
    for (int c = 0; c < NSPLIT; c++) { uint16_t b = bf16b(r); a1[c] = b; r -= bf2f(b); }
    const int Ktiles = 1 << (logK - 4);
    int klo = k & 15;
    int tile = (m >> 4) * Ktiles + (k >> 4);
    int lane = (m & 7) * 4 + ((klo & 7) >> 1);
    int slot = ((m >> 3) & 1) + ((klo >> 3) << 1);
    size_t off = (size_t)tile * 128 + lane * 4 + slot;
    c0[off] = (uint32_t)a0[0] | ((uint32_t)a1[0] << 16);
    if (NSPLIT >= 2) c1[off] = (uint32_t)a0[1] | ((uint32_t)a1[1] << 16);
    if (NSPLIT >= 3) c2[off] = (uint32_t)a0[2] | ((uint32_t)a1[2] << 16);
}

template <int NSPLIT>
__global__ void splitB_bf(const float* __restrict__ W,
                          uint32_t* __restrict__ c0, uint32_t* __restrict__ c1,
                          uint32_t* __restrict__ c2,
                          int KN2, int logN, int K) {
    int idx = blockIdx.x * 256 + threadIdx.x;
    if (idx >= KN2) return;
    int n = idx & ((1 << logN) - 1);
    int k2 = idx >> logN;
    int k = k2 << 1;
    float v0 = W[((size_t)k << logN) + n];
    float v1 = W[((size_t)(k + 1) << logN) + n];
    uint16_t a0[3], a1[3];
    float r = v0;
#pragma unroll
    for (int c = 0; c < NSPLIT; c++) { uint16_t b = bf16b(r); a0[c] = b; r -= bf2f(b); }
    r = v1;
#pragma unroll
    for (int c = 0; c < NSPLIT; c++) { uint16_t b = bf16b(r); a1[c] = b; r -= bf2f(b); }
    const int Ktiles = K >> 4;
    int klo = k & 15;
    int tile = (n >> 3) * Ktiles + (k >> 4);
    int lane = (n & 7) * 4 + ((klo & 7) >> 1);
    int slot = klo >> 3;
    size_t off = (size_t)tile * 64 + lane * 2 + slot;
    c0[off] = (uint32_t)a0[0] | ((uint32_t)a1[0] << 16);
    if (NSPLIT >= 2) c1[off] = (uint32_t)a0[1] | ((uint32_t)a1[1] << 16);
    if (NSPLIT >= 3) c2[off] = (uint32_t)a0[2] | ((uint32_t)a1[2] << 16);
}

// ---------------- 2-stage pipelined split-bf16 mma GEMM, 512 threads (R10-proven core) ----------------
// Block tile 128 x TN (TN=256 or 128), K-chunk 32. 16 warps (2 x 8), warp tile 64 x (TN/8).
// Stage u32 size = NSPLIT*(2048 + TN*16).
template <int NSPLIT, int MODE, int TN>
__global__ void __launch_bounds__(512, 1) mma_bf(
    const uint32_t* __restrict__ A0, const uint32_t* __restrict__ A1,
    const uint32_t* __restrict__ A2,
    const uint32_t* __restrict__ B0, const uint32_t* __restrict__ B1,
    const uint32_t* __restrict__ B2,
    const float* __restrict__ bias, float* __restrict__ C,
    const float* __restrict__ Xref, float* __restrict__ partial,
    int K, int N)
{
    extern __shared__ uint32_t smu[];
    constexpr int NT_N = TN / 64;                 // n-tiles per warp (4 for 256, 2 for 128)
    constexpr int STAGE_U = NSPLIT * (2048 + TN * 16);
    constexpr int BUNITS = TN * 4;                // 16B units per B component per chunk
    const int tid = threadIdx.x;
    const int wid = tid >> 5;
    const int lane = tid & 31;
    const int warpM = wid >> 3;          // 0..1
    const int warpN = wid & 7;           // 0..7
    const int rowBlock = blockIdx.y * 128;
    const int colBlock = blockIdx.x * TN;
    const int rowTile = blockIdx.y * 8;
    const int colTile = blockIdx.x * (TN / 8);
    const int Ktiles = K >> 4;
    const int nch = K >> 5;

    const uint32_t* Ac[3] = { A0, A1, A2 };
    const uint32_t* Bc[3] = { B0, B1, B2 };
    const uint32_t smem_base = (uint32_t)__cvta_generic_to_shared(smu);

    constexpr int NT = (NSPLIT == 3) ? 6 : 3;
    constexpr int TA3[6] = {0, 2, 1, 0, 1, 0};
    constexpr int TB3[6] = {2, 0, 1, 1, 0, 0};
    constexpr int TA2[3] = {1, 0, 0};
    constexpr int TB2[3] = {0, 1, 0};

    float d[4][NT_N][4];
#pragma unroll
    for (int mt = 0; mt < 4; mt++)
#pragma unroll
        for (int nt = 0; nt < NT_N; nt++)
#pragma unroll
            for (int i = 0; i < 4; i++) d[mt][nt][i] = 0.f;

    auto copy_stage = [&](int s, int c) {
        const uint32_t sb = smem_base + (uint32_t)(s * STAGE_U) * 4u;
        // A: NSPLIT*512 16B units / 512 threads
#pragma unroll
        for (int j = 0; j < NSPLIT; j++) {
            int o = j * 512 + tid;
            int comp = o >> 9;
            int rem = o & 511;
            int mt = rem >> 6;
            int w = (rem & 63) * 4;
            cpa16(sb + (uint32_t)(comp * 2048 + mt * 256 + w) * 4u,
                  Ac[comp] + ((size_t)(rowTile + mt) * Ktiles + 2 * c) * 128 + w);
        }
        // B: NSPLIT*BUNITS 16B units / 512 threads
#pragma unroll
        for (int j = 0; j < NSPLIT * BUNITS / 512; j++) {
            int o = j * 512 + tid;
            int comp = o / BUNITS;
            int rem = o - comp * BUNITS;
            int nt = rem >> 5;
            int w = (rem & 31) * 4;
            cpa16(sb + (uint32_t)(NSPLIT * 2048 + comp * (TN * 16) + nt * 128 + w) * 4u,
                  Bc[comp] + ((size_t)(colTile + nt) * Ktiles + 2 * c) * 64 + w);
        }
    };

    auto compute_stage = [&](int s) {
        const uint32_t* sA = smu + s * STAGE_U;
        const uint32_t* sB = sA + NSPLIT * 2048;
#pragma unroll
        for (int ks = 0; ks < 2; ks++) {
            uint32_t bf[NSPLIT][NT_N][2];
#pragma unroll
            for (int nt = 0; nt < NT_N; nt++)
#pragma unroll
                for (int cc = 0; cc < NSPLIT; cc++) {
                    const uint32_t* p = &sB[cc * (TN * 16) + (warpN * NT_N + nt) * 128 + ks * 64 + lane * 2];
                    bf[cc][nt][0] = p[0];
                    bf[cc][nt][1] = p[1];
                }
#pragma unroll
            for (int mt = 0; mt < 4; mt++) {
                uint32_t af[NSPLIT][4];
#pragma unroll
                for (int cc = 0; cc < NSPLIT; cc++) {
                    const uint32_t* p = &sA[cc * 2048 + (warpM * 4 + mt) * 256 + ks * 128 + lane * 4];
                    af[cc][0] = p[0]; af[cc][1] = p[1]; af[cc][2] = p[2]; af[cc][3] = p[3];
                }
#pragma unroll
                for (int nt = 0; nt < NT_N; nt++) {
#pragma unroll
                    for (int t = 0; t < NT; t++) {
                        int ta = (NSPLIT == 3) ? TA3[t] : TA2[t];
                        int tb = (NSPLIT == 3) ? TB3[t] : TB2[t];
                        mma16(d[mt][nt], af[ta], bf[tb][nt]);
                    }
                }
            }
        }
    };

    // prologue: 2 stages (R10-proven)
    const int pre = (nch < 2) ? nch : 2;
    for (int s = 0; s < pre; s++) {
        copy_stage(s, s);
        asm volatile("cp.async.commit_group;" ::: "memory");
    }
    for (int c = 0; c < nch; c++) {
        if (c < nch - 1) asm volatile("cp.async.wait_group 1;" ::: "memory");
        else             asm volatile("cp.async.wait_group 0;" ::: "memory");
        __syncthreads();
        compute_stage(c & 1);
        if (c + 2 < nch) {
            __syncthreads();
            copy_stage(c & 1, c + 2);
            asm volatile("cp.async.commit_group;" ::: "memory");
        }
    }

    // ---- epilogue (proven m16n8 C-fragment mapping) ----
    float2 bb[NT_N];
#pragma unroll
    for (int nt = 0; nt < NT_N; nt++)
        bb[nt] = *reinterpret_cast<const float2*>(
            &bias[colBlock + (warpN * NT_N + nt) * 8 + (lane & 3) * 2]);

    if (MODE == 0) {
#pragma unroll
        for (int mt = 0; mt < 4; mt++) {
            const int r0 = rowBlock + warpM * 64 + mt * 16 + (lane >> 2);
#pragma unroll
            for (int nt = 0; nt < NT_N; nt++) {
                const int col = colBlock + (warpN * NT_N + nt) * 8 + (lane & 3) * 2;
                float2 v0, v1;
                v0.x = fmaxf(d[mt][nt][0] + bb[nt].x, 0.f);
                v0.y = fmaxf(d[mt][nt][1] + bb[nt].y, 0.f);
                v1.x = fmaxf(d[mt][nt][2] + bb[nt].x, 0.f);
                v1.y = fmaxf(d[mt][nt][3] + bb[nt].y, 0.f);
                *reinterpret_cast<float2*>(&C[(size_t)r0 * N + col]) = v0;
                *reinterpret_cast<float2*>(&C[(size_t)(r0 + 8) * N + col]) = v1;
            }
        }
    } else {
        float msum = 0.f;
#pragma unroll
        for (int mt = 0; mt < 4; mt++) {
            const int r0 = rowBlock + warpM * 64 + mt * 16 + (lane >> 2);
#pragma unroll
            for (int nt = 0; nt < NT_N; nt++) {
                const int col = colBlock + (warpN * NT_N + nt) * 8 + (lane & 3) * 2;
                float2 x0 = *reinterpret_cast<const float2*>(&Xref[(size_t)r0 * N + col]);
                float2 x1 = *reinterpret_cast<const float2*>(&Xref[(size_t)(r0 + 8) * N + col]);
                float e;
                e = d[mt][nt][0] + bb[nt].x - x0.x; msum = fmaf(e, e, msum);
                e = d[mt][nt][1] + bb[nt].y - x0.y; msum = fmaf(e, e, msum);
                e = d[mt][nt][2] + bb[nt].x - x1.x; msum = fmaf(e, e, msum);
                e = d[mt][nt][3] + bb[nt].y - x1.y; msum = fmaf(e, e, msum);
            }
        }
        __syncthreads();
        float* red = reinterpret_cast<float*>(smu);
        red[tid] = msum;
        __syncthreads();
        for (int o = 256; o > 0; o >>= 1) {
            if (tid < o) red[tid] += red[tid + o];
            __syncthreads();
        }
        if (tid == 0) partial[blockIdx.y * gridDim.x + blockIdx.x] = red[0];
    }
}

// ---------------- small-N fp32 scalar GEMM (z layer, N=32) ----------------
__global__ __launch_bounds__(256) void gemm_relu(
    const float* __restrict__ A, const float* __restrict__ W,
    const float* __restrict__ bias, float* __restrict__ C,
    int M, int K, int N, int doRelu)
{
    __shared__ float As[BK][BM];
    __shared__ float Wsm[BK][BN];
    const int tid = threadIdx.x;
    const int rowBlock = blockIdx.y * BM;
    const int colBlock = blockIdx.x * BN;
    const int tx = tid & 15;
    const int ty = tid >> 4;
    const int rBase = ty * 8;
    const int cBase = tx * 4;

    float acc[8][4];
#pragma unroll
    for (int i = 0; i < 8; i++)
#pragma unroll
        for (int j = 0; j < 4; j++) acc[i][j] = 0.f;

    const int aRow0 = tid >> 2;
    const int aF4   = tid & 3;
    const int wK    = tid >> 4;
    const int wC    = (tid & 15) * 4;

    for (int k0 = 0; k0 < K; k0 += BK) {
#pragma unroll
        for (int h = 0; h < 2; h++) {
            int r = aRow0 + h * 64;
            float4 v = *reinterpret_cast<const float4*>(
                &A[(size_t)(rowBlock + r) * K + k0 + aF4 * 4]);
            As[aF4 * 4 + 0][r] = v.x;
            As[aF4 * 4 + 1][r] = v.y;
            As[aF4 * 4 + 2][r] = v.z;
            As[aF4 * 4 + 3][r] = v.w;
        }
        {
            int col = colBlock + wC;
            float4 v = make_float4(0.f, 0.f, 0.f, 0.f);
            if (col + 3 < N) {
                v = *reinterpret_cast<const float4*>(&W[(size_t)(k0 + wK) * N + col]);
            } else {
                float tmp[4] = {0.f, 0.f, 0.f, 0.f};
                for (int j = 0; j < 4; j++)
                    if (col + j < N) tmp[j] = W[(size_t)(k0 + wK) * N + col + j];
                v = make_float4(tmp[0], tmp[1], tmp[2], tmp[3]);
            }
            *reinterpret_cast<float4*>(&Wsm[wK][wC]) = v;
        }
        __syncthreads();
#pragma unroll
        for (int kk = 0; kk < BK; kk++) {
            float a[8], b[4];
#pragma unroll
            for (int i = 0; i < 8; i++) a[i] = As[kk][rBase + i];
#pragma unroll
            for (int j = 0; j < 4; j++) b[j] = Wsm[kk][cBase + j];
#pragma unroll
            for (int i = 0; i < 8; i++)
#pragma unroll
                for (int j = 0; j < 4; j++) acc[i][j] = fmaf(a[i], b[j], acc[i][j]);
        }
        __syncthreads();
    }
#pragma unroll
    for (int i = 0; i < 8; i++) {
        int row = rowBlock + rBase + i;
#pragma unroll
        for (int j = 0; j < 4; j++) {
            int col = colBlock + cBase + j;
            if (col < N) {
                float v = acc[i][j] + bias[col];
                if (doRelu) v = fmaxf(v, 0.f);
                C[(size_t)row * N + col] = v;
            }
        }
    }
}

// ---------------- pass A ----------------
__global__ __launch_bounds__(128) void passA(
    const float* __restrict__ z, const float* __restrict__ t1,
    const float* __restrict__ clus, float* __restrict__ q,
    int* __restrict__ pred, float* __restrict__ scon,
    float* __restrict__ out, int out_size)
{
    __shared__ float cs[K_C * NZ_C];
    const int tid = threadIdx.x;
    for (int i = tid; i < K_C * NZ_C; i += 128) cs[i] = clus[i];
    __syncthreads();

    const int n = blockIdx.x * 128 + tid;
    if (n >= N_PTS) return;

    const float tx = t1[n * 3 + 0] * 0.01f;
    const float ty = t1[n * 3 + 1] * 0.01f;
    const float tz = t1[n * 3 + 2] * 0.01f;
    const float cm = tx * ty * tz * 0.99f + 1.0f;

    float zp[NZ_C];
    const float* zr = &z[(size_t)n * NZ_C];
    float mean = 0.f;
#pragma unroll
    for (int i = 0; i < NZ_C; i++) { zp[i] = zr[i] * cm; mean += zp[i]; }
    mean *= (1.0f / NZ_C);
    float var = 0.f;
#pragma unroll
    for (int i = 0; i < NZ_C; i++) { float dd = zp[i] - mean; var += dd * dd; }
    var *= (1.0f / (NZ_C - 1));
    const float invstd = 1.0f / sqrtf(var);
#pragma unroll
    for (int i = 0; i < NZ_C; i++) zp[i] = (zp[i] - mean) * invstd;

    float qsum = 0.f;
    float best = -1.f;
    int bestk = 0;
    for (int k = 0; k < K_C; k++) {
        const float* c = &cs[k * NZ_C];
        float dsum = 0.f;
#pragma unroll
        for (int i = 0; i < NZ_C; i++) { float df = zp[i] - c[i]; dsum = fmaf(df, df, dsum); }
        float qr = EPS_C + dsum;
        q[(size_t)k * N_PTS + n] = qr;
        qsum += qr;
        if (qr > best) { best = qr; bestk = k; }
    }
    const float inv = 1.0f / qsum;
    float s = 0.f;
    for (int k = 0; k < K_C; k++) {
        float qn = q[(size_t)k * N_PTS + n] * inv;
        q[(size_t)k * N_PTS + n] = qn;
        float l = logf(qn);
        float t = 1.0f - qn;
        float neg_temp = t * t * (-l) * (float)N_PTS;
        s += 1.0f / sqrtf(neg_temp);
    }
    pred[n] = bestk;
    scon[n] = s;
    if (n < out_size) out[n] = (float)bestk;
    atomicAdd(&g_cnt[bestk], 1);
}

// ---------------- reductions ----------------
__global__ void ureduce(const float* __restrict__ q) {
    __shared__ float sh[256];
    const int k = blockIdx.x;
    float s = 0.f;
    for (int n = threadIdx.x; n < N_PTS; n += 256) s += q[(size_t)k * N_PTS + n];
    sh[threadIdx.x] = s;
    __syncthreads();
    for (int o = 128; o > 0; o >>= 1) {
        if (threadIdx.x < o) sh[threadIdx.x] += sh[threadIdx.x + o];
        __syncthreads();
    }
    if (threadIdx.x == 0) g_u[k] = sh[0];
}

__global__ void sreduce(const float* __restrict__ scon) {
    __shared__ float sh[256];
    float s = 0.f;
    for (int n = threadIdx.x; n < N_PTS; n += 256) s += scon[n];
    sh[threadIdx.x] = s;
    __syncthreads();
    for (int o = 128; o > 0; o >>= 1) {
        if (threadIdx.x < o) sh[threadIdx.x] += sh[threadIdx.x + o];
        __syncthreads();
    }
    if (threadIdx.x == 0) g_S = sh[0];
}

__global__ void passB(const float* __restrict__ clus) {
    __shared__ float sh[256];
    const int tid = threadIdx.x;
    float s = 0.f;
    for (int p = tid; p < K_C * K_C; p += 256) {
        int i = p / K_C, j = p - i * K_C;
        const float* a = &clus[i * NZ_C];
        const float* b = &clus[j * NZ_C];
        float dsum = 0.f;
#pragma unroll
        for (int t = 0; t < NZ_C; t++) { float df = a[t] - b[t]; dsum = fmaf(df, df, dsum); }
        s += dsum;
    }
    sh[tid] = s;
    __syncthreads();
    for (int o = 128; o > 0; o >>= 1) {
        if (tid < o) sh[tid] += sh[tid + o];
        __syncthreads();
    }
    if (tid == 0) {
        float md = sh[0] / (float)(K_C * K_C - K_C);
        g_uloss = 0.01f / md;

        float un[K_C], vn[K_C];
        float um = 0.f;
        for (int k = 0; k < K_C; k++) um += g_u[k];
        um /= (float)K_C;
        float uv = 0.f;
        for (int k = 0; k < K_C; k++) { float dd = g_u[k] - um; uv += dd * dd; }
        uv /= (float)(K_C - 1);
        float uis = 1.0f / sqrtf(uv);
        for (int k = 0; k < K_C; k++) un[k] = (g_u[k] - um) * uis;

        float S = g_S;
        float vm = 0.f;
        for (int k = 0; k < K_C; k++) {
            float nc = (g_cnt[k] > 0) ? (float)g_cnt[k] : 1.0f;
            vn[k] = sqrtf(nc) * S;
            vm += vn[k];
        }
        vm /= (float)K_C;
        float vv = 0.f;
        for (int k = 0; k < K_C; k++) { float dd = vn[k] - vm; vv += dd * dd; }
        vv /= (float)(K_C - 1);
        float vis = 1.0f / sqrtf(vv);
        for (int k = 0; k < K_C; k++) vn[k] = (vn[k] - vm) * vis;

        float umin = un[0], vmin = vn[0];
        for (int k = 1; k < K_C; k++) {
            umin = fminf(umin, un[k]);
            vmin = fminf(vmin, vn[k]);
        }
        for (int k = 0; k < K_C; k++) {
            g_f[k] = (un[k] - umin + 0.001f) + (vn[k] - vmin + 0.001f) + 1.0f;
        }
    }
}

__global__ __launch_bounds__(128) void passC(const float* __restrict__ q,
                                             float* __restrict__ klp) {
    __shared__ float fsh[K_C];
    __shared__ float sh[128];
    const int tid = threadIdx.x;
    for (int i = tid; i < K_C; i += 128) fsh[i] = g_f[i];
    __syncthreads();
    const int n = blockIdx.x * 128 + tid;
    float kl = 0.f;
    float ws = 0.f;
    for (int k = 0; k < K_C; k++) {
        float qv = q[(size_t)k * N_PTS + n];
        ws += qv * qv / fsh[k];
    }
    float inv = 1.0f / ws;
    for (int k = 0; k < K_C; k++) {
        float qv = q[(size_t)k * N_PTS + n];
        float p = qv * qv / fsh[k] * inv;
        kl += p * (logf(p) - logf(qv));
    }
    sh[tid] = kl;
    __syncthreads();
    for (int o = 64; o > 0; o >>= 1) {
        if (tid < o) sh[tid] += sh[tid + o];
        __syncthreads();
    }
    if (tid == 0) klp[blockIdx.x] = sh[0];
}

__global__ void finalk(float* __restrict__ out, int out_size) {
    __shared__ float sh[256];
    __shared__ float tot[2];
    const int tid = threadIdx.x;
    float s = 0.f;
    for (int i = tid; i < MSE_PARTIALS; i += 256) s += g_msep[i];
    sh[tid] = s;
    __syncthreads();
    for (int o = 128; o > 0; o >>= 1) {
        if (tid < o) sh[tid] += sh[tid + o];
        __syncthreads();
    }
    if (tid == 0) tot[0] = sh[0];
    __syncthreads();
    s = 0.f;
    for (int i = tid; i < MBLK; i += 256) s += g_klp[i];
    sh[tid] = s;
    __syncthreads();
    for (int o = 128; o > 0; o >>= 1) {
        if (tid < o) sh[tid] += sh[tid + o];
        __syncthreads();
    }
    if (tid == 0) tot[1] = sh[0];
    __syncthreads();
    if (tid == 0) {
        float re_loss = tot[0] / ((float)N_PTS * (float)N_IN_C);
        float kl_loss = tot[1] / ((float)N_PTS * (float)K_C) * 0.01f;
        float loss = kl_loss + re_loss + g_uloss;
        if (out_size > N_PTS) out[N_PTS] = loss;
    }
}

// ---------------- launch ----------------
extern "C" void kernel_launch(void* const* d_in, const int* in_sizes, int n_in,
                              void* d_out, int out_size) {
    const float* x    = (const float*)d_in[0];
    const float* t1   = (const float*)d_in[1];
    const float* clus = (const float*)d_in[2];
    const float* We1  = (const float*)d_in[3];
    const float* be1  = (const float*)d_in[4];
    const float* We2  = (const float*)d_in[5];
    const float* be2  = (const float*)d_in[6];
    const float* We3  = (const float*)d_in[7];
    const float* be3  = (const float*)d_in[8];
    const float* Wz   = (const float*)d_in[9];
    const float* bz   = (const float*)d_in[10];
    const float* Wd1  = (const float*)d_in[11];
    const float* bd1  = (const float*)d_in[12];
    const float* Wd2  = (const float*)d_in[13];
    const float* bd2  = (const float*)d_in[14];
    const float* Wd3  = (const float*)d_in[15];
    const float* bd3  = (const float*)d_in[16];
    const float* Wxb  = (const float*)d_in[17];
    const float* bxb  = (const float*)d_in[18];
    float* out = (float*)d_out;

    float *bufA, *bufB, *zbuf, *qbuf, *scon, *msep, *klp;
    uint32_t *cA0, *cA1, *cA2, *cB0, *cB1, *cB2;
    int *pred;
    cudaGetSymbolAddress((void**)&bufA, g_bufA);
    cudaGetSymbolAddress((void**)&bufB, g_bufB);
    cudaGetSymbolAddress((void**)&cA0, g_cA0);
    cudaGetSymbolAddress((void**)&cA1, g_cA1);
    cudaGetSymbolAddress((void**)&cA2, g_cA2);
    cudaGetSymbolAddress((void**)&cB0, g_cB0);
    cudaGetSymbolAddress((void**)&cB1, g_cB1);
    cudaGetSymbolAddress((void**)&cB2, g_cB2);
    cudaGetSymbolAddress((void**)&zbuf, g_zbuf);
    cudaGetSymbolAddress((void**)&qbuf, g_q);
    cudaGetSymbolAddress((void**)&pred, g_pred);
    cudaGetSymbolAddress((void**)&scon, g_Scon);
    cudaGetSymbolAddress((void**)&msep, g_msep);
    cudaGetSymbolAddress((void**)&klp,  g_klp);

    // dyn smem: 2 stages * NSPLIT*(2048 + TN*16) u32 * 4B
    const int DS3_256 = 2 * 3 * (2048 + 256 * 16) * 4;  // 147456
    const int DS3_128 = 2 * 3 * (2048 + 128 * 16) * 4;  //  98304
    const int DS2_256 = 2 * 2 * (2048 + 256 * 16) * 4;  //  98304
    const int DS2_128 = 2 * 2 * (2048 + 128 * 16) * 4;  //  65536
    cudaFuncSetAttribute(mma_bf<3, 0, 256>, cudaFuncAttributeMaxDynamicSharedMemorySize, DS3_256);
    cudaFuncSetAttribute(mma_bf<3, 0, 128>, cudaFuncAttributeMaxDynamicSharedMemorySize, DS3_128);
    cudaFuncSetAttribute(mma_bf<2, 0, 256>, cudaFuncAttributeMaxDynamicSharedMemorySize, DS2_256);
    cudaFuncSetAttribute(mma_bf<2, 0, 128>, cudaFuncAttributeMaxDynamicSharedMemorySize, DS2_128);
    cudaFuncSetAttribute(mma_bf<2, 1, 256>, cudaFuncAttributeMaxDynamicSharedMemorySize, DS2_256);

    init_kernel<<<1, 128>>>();
    auto nb = [](int elems) { return (elems + 255) / 256; };

    // ---- encoder: 3-way bf16 split, 6 terms ----
    splitA_bf<3><<<nb(N_PTS * 512), 256>>>(x, cA0, cA1, cA2, N_PTS * 512, 10);
    splitB_bf<3><<<nb(512 * E1_C), 256>>>(We1, cB0, cB1, cB2, 512 * E1_C, 9, N_IN_C);
    mma_bf<3, 0, 128><<<dim3(E1_C / 128, MBLK), 512, DS3_128>>>(cA0, cA1, cA2, cB0, cB1, cB2,
        be1, bufA, nullptr, nullptr, N_IN_C, E1_C);

    splitA_bf<3><<<nb(N_PTS * 256), 256>>>(bufA, cA0, cA1, cA2, N_PTS * 256, 9);
    splitB_bf<3><<<nb(256 * E2_C), 256>>>(We2, cB0, cB1, cB2, 256 * E2_C, 9, E1_C);
    mma_bf<3, 0, 128><<<dim3(E2_C / 128, MBLK), 512, DS3_128>>>(cA0, cA1, cA2, cB0, cB1, cB2,
        be2, bufB, nullptr, nullptr, E1_C, E2_C);

    splitA_bf<3><<<nb(N_PTS * 256), 256>>>(bufB, cA0, cA1, cA2, N_PTS * 256, 9);
    splitB_bf<3><<<nb(256 * E3_C), 256>>>(We3, cB0, cB1, cB2, 256 * E3_C, 11, E2_C);
    mma_bf<3, 0, 256><<<dim3(E3_C / 256, MBLK), 512, DS3_256>>>(cA0, cA1, cA2, cB0, cB1, cB2,
        be3, bufA, nullptr, nullptr, E2_C, E3_C);

    // z layer (scalar fp32, N=32)
    gemm_relu<<<dim3(1, N_PTS / BM), 256>>>(bufA, Wz, bz, zbuf, N_PTS, E3_C, NZ_C, 0);

    // ---- decoder: 2-way bf16 split, 3 terms ----
    splitA_bf<2><<<nb(N_PTS * 16), 256>>>(zbuf, cA0, cA1, nullptr, N_PTS * 16, 5);
    splitB_bf<2><<<nb(16 * D1_C), 256>>>(Wd1, cB0, cB1, nullptr, 16 * D1_C, 11, NZ_C);
    mma_bf<2, 0, 256><<<dim3(D1_C / 256, MBLK), 512, DS2_256>>>(cA0, cA1, nullptr, cB0, cB1, nullptr,
        bd1, bufB, nullptr, nullptr, NZ_C, D1_C);

    splitA_bf<2><<<nb(N_PTS * 1024), 256>>>(bufB, cA0, cA1, nullptr, N_PTS * 1024, 11);
    splitB_bf<2><<<nb(1024 * D2_C), 256>>>(Wd2, cB0, cB1, nullptr, 1024 * D2_C, 9, D1_C);
    mma_bf<2, 0, 128><<<dim3(D2_C / 128, MBLK), 512, DS2_128>>>(cA0, cA1, nullptr, cB0, cB1, nullptr,
        bd2, bufA, nullptr, nullptr, D1_C, D2_C);

    splitA_bf<2><<<nb(N_PTS * 256), 256>>>(bufA, cA0, cA1, nullptr, N_PTS * 256, 9);
    splitB_bf<2><<<nb(256 * D3_C), 256>>>(Wd3, cB0, cB1, nullptr, 256 * D3_C, 9, D2_C);
    mma_bf<2, 0, 128><<<dim3(D3_C / 128, MBLK), 512, DS2_128>>>(cA0, cA1, nullptr, cB0, cB1, nullptr,
        bd3, bufB, nullptr, nullptr, D2_C, D3_C);

    splitA_bf<2><<<nb(N_PTS * 256), 256>>>(bufB, cA0, cA1, nullptr, N_PTS * 256, 9);
    splitB_bf<2><<<nb(256 * N_IN_C), 256>>>(Wxb, cB0, cB1, nullptr, 256 * N_IN_C, 10, D3_C);
    mma_bf<2, 1, 256><<<dim3(N_IN_C / 256, MBLK), 512, DS2_256>>>(cA0, cA1, nullptr, cB0, cB1, nullptr,
        bxb, nullptr, x, msep, D3_C, N_IN_C);

    // ---- clustering + losses ----
    passA<<<MBLK, 128>>>(zbuf, t1, clus, qbuf, pred, scon, out, out_size);
    ureduce<<<K_C, 256>>>(qbuf);
    sreduce<<<1, 256>>>(scon);
    passB<<<1, 256>>>(clus);
    passC<<<MBLK, 128>>>(qbuf, klp);
    finalk<<<1, 256>>>(out, out_size);
}

// round 16
// speedup vs baseline: 1.5848x; 1.0419x over previous
#include <cuda_runtime.h>
#include <cuda_bf16.h>
#include <math.h>
#include <stdint.h>
#include <string.h>

// ---------------- problem constants ----------------
#define N_PTS   29696
#define N_IN_C  1024
#define E1_C    512
#define E2_C    512
#define E3_C    2048
#define NZ_C    32
#define D1_C    2048
#define D2_C    512
#define D3_C    512
#define K_C     100
#define EPS_C   1e-5f

#define MBLK    (N_PTS / 128)                   // 232
#define MSE_PARTIALS (MBLK * (N_IN_C / 256))    // 928

// ---------------- scratch ----------------
__device__ float g_bufA[(size_t)N_PTS * 2048];
__device__ float g_bufB[(size_t)N_PTS * 2048];
__device__ uint32_t g_cA0[(size_t)N_PTS * 1024];
__device__ uint32_t g_cA1[(size_t)N_PTS * 1024];
__device__ uint32_t g_cA2[(size_t)N_PTS * 512];
__device__ uint32_t g_cB0[2048 * 1024];
__device__ uint32_t g_cB1[2048 * 1024];
__device__ uint32_t g_cB2[2048 * 1024];
__device__ float g_zbuf[(size_t)N_PTS * NZ_C];
__device__ float g_q[(size_t)K_C * N_PTS];
__device__ int   g_pred[N_PTS];
__device__ float g_Scon[N_PTS];
__device__ float g_u[K_C];
__device__ float g_f[K_C];
__device__ int   g_cnt[K_C];
__device__ float g_S;
__device__ float g_uloss;
__device__ float g_msep[MSE_PARTIALS];
__device__ float g_klp[MBLK];

__global__ void init_kernel() {
    int t = threadIdx.x;
    if (t < K_C) g_cnt[t] = 0;
}

// ---------------- helpers ----------------
__device__ __forceinline__ uint16_t bf16b(float x) {
    __nv_bfloat16 h = __float2bfloat16_rn(x);
    return *reinterpret_cast<uint16_t*>(&h);
}
__device__ __forceinline__ float bf2f(uint16_t b) {
    __nv_bfloat16 h;
    memcpy(&h, &b, 2);
    return __bfloat162float(h);
}
__device__ __forceinline__ void mma16(float* d, const uint32_t* a, const uint32_t* b) {
    asm volatile(
        "mma.sync.aligned.m16n8k16.row.col.f32.bf16.bf16.f32 "
        "{%0,%1,%2,%3}, {%4,%5,%6,%7}, {%8,%9}, {%0,%1,%2,%3};"
        : "+f"(d[0]), "+f"(d[1]), "+f"(d[2]), "+f"(d[3])
        : "r"(a[0]), "r"(a[1]), "r"(a[2]), "r"(a[3]), "r"(b[0]), "r"(b[1]));
}
__device__ __forceinline__ void cpa16(uint32_t dst_smem, const void* src) {
    asm volatile("cp.async.cg.shared.global [%0], [%1], 16;"
                 :: "r"(dst_smem), "l"(__cvta_generic_to_global(src)));
}

// ---------------- split kernels ----------------
template <int NSPLIT>
__global__ void splitA_bf(const float* __restrict__ src,
                          uint32_t* __restrict__ c0, uint32_t* __restrict__ c1,
                          uint32_t* __restrict__ c2,
                          int MK2, int logK) {
    int idx = blockIdx.x * 256 + threadIdx.x;
    if (idx >= MK2) return;
    const int K2 = 1 << (logK - 1);
    int k2 = idx & (K2 - 1);
    int m = idx >> (logK - 1);
    int k = k2 << 1;
    float v0 = src[((size_t)m << logK) + k];
    float v1 = src[((size_t)m << logK) + k + 1];
    uint16_t a0[3], a1[3];
    float r = v0;
#pragma unroll
    for (int c = 0; c < NSPLIT; c++) { uint16_t b = bf16b(r); a0[c] = b; r -= bf2f(b); }
    r = v1;
#pragma unroll
    for (int c = 0; c < NSPLIT; c++) { uint16_t b = bf16b(r); a1[c] = b; r -= bf2f(b); }
    const int Ktiles = 1 << (logK - 4);
    int klo = k & 15;
    int tile = (m >> 4) * Ktiles + (k >> 4);
    int lane = (m & 7) * 4 + ((klo & 7) >> 1);
    int slot = ((m >> 3) & 1) + ((klo >> 3) << 1);
    size_t off = (size_t)tile * 128 + lane * 4 + slot;
    c0[off] = (uint32_t)a0[0] | ((uint32_t)a1[0] << 16);
    if (NSPLIT >= 2) c1[off] = (uint32_t)a0[1] | ((uint32_t)a1[1] << 16);
    if (NSPLIT >= 3) c2[off] = (uint32_t)a0[2] | ((uint32_t)a1[2] << 16);
}

template <int NSPLIT>
__global__ void splitB_bf(const float* __restrict__ W,
                          uint32_t* __restrict__ c0, uint32_t* __restrict__ c1,
                          uint32_t* __restrict__ c2,
                          int KN2, int logN, int K) {
    int idx = blockIdx.x * 256 + threadIdx.x;
    if (idx >= KN2) return;
    int n = idx & ((1 << logN) - 1);
    int k2 = idx >> logN;
    int k = k2 << 1;
    float v0 = W[((size_t)k << logN) + n];
    float v1 = W[((size_t)(k + 1) << logN) + n];
    uint16_t a0[3], a1[3];
    float r = v0;
#pragma unroll
    for (int c = 0; c < NSPLIT; c++) { uint16_t b = bf16b(r); a0[c] = b; r -= bf2f(b); }
    r = v1;
#pragma unroll
    for (int c = 0; c < NSPLIT; c++) { uint16_t b = bf16b(r); a1[c] = b; r -= bf2f(b); }
    const int Ktiles = K >> 4;
    int klo = k & 15;
    int tile = (n >> 3) * Ktiles + (k >> 4);
    int lane = (n & 7) * 4 + ((klo & 7) >> 1);
    int slot = klo >> 3;
    size_t off = (size_t)tile * 64 + lane * 2 + slot;
    c0[off] = (uint32_t)a0[0] | ((uint32_t)a1[0] << 16);
    if (NSPLIT >= 2) c1[off] = (uint32_t)a0[1] | ((uint32_t)a1[1] << 16);
    if (NSPLIT >= 3) c2[off] = (uint32_t)a0[2] | ((uint32_t)a1[2] << 16);
}

// ---------------- 2-stage pipelined split-bf16 mma GEMM, 512 threads ----------------
// Block tile 128 x TN. 16 warps (2 x 8), warp tile 64 x (TN/8).
template <int NSPLIT, int MODE, int TN>
__global__ void __launch_bounds__(512, 1) mma_bf(
    const uint32_t* __restrict__ A0, const uint32_t* __restrict__ A1,
    const uint32_t* __restrict__ A2,
    const uint32_t* __restrict__ B0, const uint32_t* __restrict__ B1,
    const uint32_t* __restrict__ B2,
    const float* __restrict__ bias, float* __restrict__ C,
    const float* __restrict__ Xref, float* __restrict__ partial,
    int K, int N)
{
    extern __shared__ uint32_t smu[];
    constexpr int NT_N = TN / 64;
    constexpr int STAGE_U = NSPLIT * (2048 + TN * 16);
    constexpr int BUNITS = TN * 4;
    const int tid = threadIdx.x;
    const int wid = tid >> 5;
    const int lane = tid & 31;
    const int warpM = wid >> 3;
    const int warpN = wid & 7;
    const int rowBlock = blockIdx.y * 128;
    const int colBlock = blockIdx.x * TN;
    const int rowTile = blockIdx.y * 8;
    const int colTile = blockIdx.x * (TN / 8);
    const int Ktiles = K >> 4;
    const int nch = K >> 5;

    const uint32_t* Ac[3] = { A0, A1, A2 };
    const uint32_t* Bc[3] = { B0, B1, B2 };
    const uint32_t smem_base = (uint32_t)__cvta_generic_to_shared(smu);

    constexpr int NT = (NSPLIT == 3) ? 6 : 3;
    constexpr int TA3[6] = {0, 2, 1, 0, 1, 0};
    constexpr int TB3[6] = {2, 0, 1, 1, 0, 0};
    constexpr int TA2[3] = {1, 0, 0};
    constexpr int TB2[3] = {0, 1, 0};

    float d[4][NT_N][4];
#pragma unroll
    for (int mt = 0; mt < 4; mt++)
#pragma unroll
        for (int nt = 0; nt < NT_N; nt++)
#pragma unroll
            for (int i = 0; i < 4; i++) d[mt][nt][i] = 0.f;

    auto copy_stage = [&](int s, int c) {
        const uint32_t sb = smem_base + (uint32_t)(s * STAGE_U) * 4u;
#pragma unroll
        for (int j = 0; j < NSPLIT; j++) {
            int o = j * 512 + tid;
            int comp = o >> 9;
            int rem = o & 511;
            int mt = rem >> 6;
            int w = (rem & 63) * 4;
            cpa16(sb + (uint32_t)(comp * 2048 + mt * 256 + w) * 4u,
                  Ac[comp] + ((size_t)(rowTile + mt) * Ktiles + 2 * c) * 128 + w);
        }
#pragma unroll
        for (int j = 0; j < NSPLIT * BUNITS / 512; j++) {
            int o = j * 512 + tid;
            int comp = o / BUNITS;
            int rem = o - comp * BUNITS;
            int nt = rem >> 5;
            int w = (rem & 31) * 4;
            cpa16(sb + (uint32_t)(NSPLIT * 2048 + comp * (TN * 16) + nt * 128 + w) * 4u,
                  Bc[comp] + ((size_t)(colTile + nt) * Ktiles + 2 * c) * 64 + w);
        }
    };

    auto compute_stage = [&](int s) {
        const uint32_t* sA = smu + s * STAGE_U;
        const uint32_t* sB = sA + NSPLIT * 2048;
#pragma unroll
        for (int ks = 0; ks < 2; ks++) {
            uint32_t bf[NSPLIT][NT_N][2];
#pragma unroll
            for (int nt = 0; nt < NT_N; nt++)
#pragma unroll
                for (int cc = 0; cc < NSPLIT; cc++) {
                    const uint32_t* p = &sB[cc * (TN * 16) + (warpN * NT_N + nt) * 128 + ks * 64 + lane * 2];
                    bf[cc][nt][0] = p[0];
                    bf[cc][nt][1] = p[1];
                }
#pragma unroll
            for (int mt = 0; mt < 4; mt++) {
                uint32_t af[NSPLIT][4];
#pragma unroll
                for (int cc = 0; cc < NSPLIT; cc++) {
                    const uint32_t* p = &sA[cc * 2048 + (warpM * 4 + mt) * 256 + ks * 128 + lane * 4];
                    af[cc][0] = p[0]; af[cc][1] = p[1]; af[cc][2] = p[2]; af[cc][3] = p[3];
                }
#pragma unroll
                for (int nt = 0; nt < NT_N; nt++) {
#pragma unroll
                    for (int t = 0; t < NT; t++) {
                        int ta = (NSPLIT == 3) ? TA3[t] : TA2[t];
                        int tb = (NSPLIT == 3) ? TB3[t] : TB2[t];
                        mma16(d[mt][nt], af[ta], bf[tb][nt]);
                    }
                }
            }
        }
    };

    const int pre = (nch < 2) ? nch : 2;
    for (int s = 0; s < pre; s++) {
        copy_stage(s, s);
        asm volatile("cp.async.commit_group;" ::: "memory");
    }
    for (int c = 0; c < nch; c++) {
        if (c < nch - 1) asm volatile("cp.async.wait_group 1;" ::: "memory");
        else             asm volatile("cp.async.wait_group 0;" ::: "memory");
        __syncthreads();
        compute_stage(c & 1);
        if (c + 2 < nch) {
            __syncthreads();
            copy_stage(c & 1, c + 2);
            asm volatile("cp.async.commit_group;" ::: "memory");
        }
    }

    float2 bb[NT_N];
#pragma unroll
    for (int nt = 0; nt < NT_N; nt++)
        bb[nt] = *reinterpret_cast<const float2*>(
            &bias[colBlock + (warpN * NT_N + nt) * 8 + (lane & 3) * 2]);

    if (MODE == 0) {
#pragma unroll
        for (int mt = 0; mt < 4; mt++) {
            const int r0 = rowBlock + warpM * 64 + mt * 16 + (lane >> 2);
#pragma unroll
            for (int nt = 0; nt < NT_N; nt++) {
                const int col = colBlock + (warpN * NT_N + nt) * 8 + (lane & 3) * 2;
                float2 v0, v1;
                v0.x = fmaxf(d[mt][nt][0] + bb[nt].x, 0.f);
                v0.y = fmaxf(d[mt][nt][1] + bb[nt].y, 0.f);
                v1.x = fmaxf(d[mt][nt][2] + bb[nt].x, 0.f);
                v1.y = fmaxf(d[mt][nt][3] + bb[nt].y, 0.f);
                *reinterpret_cast<float2*>(&C[(size_t)r0 * N + col]) = v0;
                *reinterpret_cast<float2*>(&C[(size_t)(r0 + 8) * N + col]) = v1;
            }
        }
    } else {
        float msum = 0.f;
#pragma unroll
        for (int mt = 0; mt < 4; mt++) {
            const int r0 = rowBlock + warpM * 64 + mt * 16 + (lane >> 2);
#pragma unroll
            for (int nt = 0; nt < NT_N; nt++) {
                const int col = colBlock + (warpN * NT_N + nt) * 8 + (lane & 3) * 2;
                float2 x0 = *reinterpret_cast<const float2*>(&Xref[(size_t)r0 * N + col]);
                float2 x1 = *reinterpret_cast<const float2*>(&Xref[(size_t)(r0 + 8) * N + col]);
                float e;
                e = d[mt][nt][0] + bb[nt].x - x0.x; msum = fmaf(e, e, msum);
                e = d[mt][nt][1] + bb[nt].y - x0.y; msum = fmaf(e, e, msum);
                e = d[mt][nt][2] + bb[nt].x - x1.x; msum = fmaf(e, e, msum);
                e = d[mt][nt][3] + bb[nt].y - x1.y; msum = fmaf(e, e, msum);
            }
        }
        __syncthreads();
        float* red = reinterpret_cast<float*>(smu);
        red[tid] = msum;
        __syncthreads();
        for (int o = 256; o > 0; o >>= 1) {
            if (tid < o) red[tid] += red[tid + o];
            __syncthreads();
        }
        if (tid == 0) partial[blockIdx.y * gridDim.x + blockIdx.x] = red[0];
    }
}

// ---------------- dedicated z-layer scalar GEMM: 256x32 tile, no wasted FMA ----------------
// 256 threads, microtile 8x4 (ty=tid>>3: 32 row groups, tx=tid&7: 8 col groups).
// Same per-output k-accumulation order as the previous gemm_relu -> bit-identical z.
__global__ __launch_bounds__(256) void gemm_z32(
    const float* __restrict__ A, const float* __restrict__ W,
    const float* __restrict__ bias, float* __restrict__ C, int K)
{
    __shared__ float As[16][258];
    __shared__ float Ws[16][32];
    const int tid = threadIdx.x;
    const int rowBlock = blockIdx.x * 256;
    const int tx = tid & 7;
    const int ty = tid >> 3;
    const int rBase = ty * 8;
    const int cBase = tx * 4;

    float acc[8][4];
#pragma unroll
    for (int i = 0; i < 8; i++)
#pragma unroll
        for (int j = 0; j < 4; j++) acc[i][j] = 0.f;

    for (int k0 = 0; k0 < K; k0 += 16) {
        // A tile 256x16 -> transposed
#pragma unroll
        for (int h = 0; h < 4; h++) {
            float4 v = *reinterpret_cast<const float4*>(
                &A[(size_t)(rowBlock + tid) * K + k0 + h * 4]);
            As[h * 4 + 0][tid] = v.x;
            As[h * 4 + 1][tid] = v.y;
            As[h * 4 + 2][tid] = v.z;
            As[h * 4 + 3][tid] = v.w;
        }
        // W tile 16x32 (512 floats, threads 0-127 load float4)
        if (tid < 128) {
            int wK = tid >> 3;
            int wC = (tid & 7) * 4;
            float4 v = *reinterpret_cast<const float4*>(&W[(size_t)(k0 + wK) * 32 + wC]);
            *reinterpret_cast<float4*>(&Ws[wK][wC]) = v;
        }
        __syncthreads();
#pragma unroll
        for (int kk = 0; kk < 16; kk++) {
            float a[8], b[4];
#pragma unroll
            for (int i = 0; i < 8; i++) a[i] = As[kk][rBase + i];
#pragma unroll
            for (int j = 0; j < 4; j++) b[j] = Ws[kk][cBase + j];
#pragma unroll
            for (int i = 0; i < 8; i++)
#pragma unroll
                for (int j = 0; j < 4; j++) acc[i][j] = fmaf(a[i], b[j], acc[i][j]);
        }
        __syncthreads();
    }
#pragma unroll
    for (int i = 0; i < 8; i++) {
        int row = rowBlock + rBase + i;
#pragma unroll
        for (int j = 0; j < 4; j++)
            C[(size_t)row * 32 + cBase + j] = acc[i][j] + bias[cBase + j];
    }
}

// ---------------- pass A ----------------
__global__ __launch_bounds__(128) void passA(
    const float* __restrict__ z, const float* __restrict__ t1,
    const float* __restrict__ clus, float* __restrict__ q,
    int* __restrict__ pred, float* __restrict__ scon,
    float* __restrict__ out, int out_size)
{
    __shared__ float cs[K_C * NZ_C];
    const int tid = threadIdx.x;
    for (int i = tid; i < K_C * NZ_C; i += 128) cs[i] = clus[i];
    __syncthreads();

    const int n = blockIdx.x * 128 + tid;
    if (n >= N_PTS) return;

    const float tx = t1[n * 3 + 0] * 0.01f;
    const float ty = t1[n * 3 + 1] * 0.01f;
    const float tz = t1[n * 3 + 2] * 0.01f;
    const float cm = tx * ty * tz * 0.99f + 1.0f;

    float zp[NZ_C];
    const float* zr = &z[(size_t)n * NZ_C];
    float mean = 0.f;
#pragma unroll
    for (int i = 0; i < NZ_C; i++) { zp[i] = zr[i] * cm; mean += zp[i]; }
    mean *= (1.0f / NZ_C);
    float var = 0.f;
#pragma unroll
    for (int i = 0; i < NZ_C; i++) { float dd = zp[i] - mean; var += dd * dd; }
    var *= (1.0f / (NZ_C - 1));
    const float invstd = 1.0f / sqrtf(var);
#pragma unroll
    for (int i = 0; i < NZ_C; i++) zp[i] = (zp[i] - mean) * invstd;

    float qsum = 0.f;
    float best = -1.f;
    int bestk = 0;
    for (int k = 0; k < K_C; k++) {
        const float* c = &cs[k * NZ_C];
        float dsum = 0.f;
#pragma unroll
        for (int i = 0; i < NZ_C; i++) { float df = zp[i] - c[i]; dsum = fmaf(df, df, dsum); }
        float qr = EPS_C + dsum;
        q[(size_t)k * N_PTS + n] = qr;
        qsum += qr;
        if (qr > best) { best = qr; bestk = k; }
    }
    const float inv = 1.0f / qsum;
    float s = 0.f;
    for (int k = 0; k < K_C; k++) {
        float qn = q[(size_t)k * N_PTS + n] * inv;
        q[(size_t)k * N_PTS + n] = qn;
        float l = logf(qn);
        float t = 1.0f - qn;
        float neg_temp = t * t * (-l) * (float)N_PTS;
        s += 1.0f / sqrtf(neg_temp);
    }
    pred[n] = bestk;
    scon[n] = s;
    if (n < out_size) out[n] = (float)bestk;
    atomicAdd(&g_cnt[bestk], 1);
}

// ---------------- reductions ----------------
__global__ void ureduce(const float* __restrict__ q) {
    __shared__ float sh[256];
    const int k = blockIdx.x;
    float s = 0.f;
    for (int n = threadIdx.x; n < N_PTS; n += 256) s += q[(size_t)k * N_PTS + n];
    sh[threadIdx.x] = s;
    __syncthreads();
    for (int o = 128; o > 0; o >>= 1) {
        if (threadIdx.x < o) sh[threadIdx.x] += sh[threadIdx.x + o];
        __syncthreads();
    }
    if (threadIdx.x == 0) g_u[k] = sh[0];
}

__global__ void sreduce(const float* __restrict__ scon) {
    __shared__ float sh[256];
    float s = 0.f;
    for (int n = threadIdx.x; n < N_PTS; n += 256) s += scon[n];
    sh[threadIdx.x] = s;
    __syncthreads();
    for (int o = 128; o > 0; o >>= 1) {
        if (threadIdx.x < o) sh[threadIdx.x] += sh[threadIdx.x + o];
        __syncthreads();
    }
    if (threadIdx.x == 0) g_S = sh[0];
}

__global__ void passB(const float* __restrict__ clus) {
    __shared__ float sh[256];
    const int tid = threadIdx.x;
    float s = 0.f;
    for (int p = tid; p < K_C * K_C; p += 256) {
        int i = p / K_C, j = p - i * K_C;
        const float* a = &clus[i * NZ_C];
        const float* b = &clus[j * NZ_C];
        float dsum = 0.f;
#pragma unroll
        for (int t = 0; t < NZ_C; t++) { float df = a[t] - b[t]; dsum = fmaf(df, df, dsum); }
        s += dsum;
    }
    sh[tid] = s;
    __syncthreads();
    for (int o = 128; o > 0; o >>= 1) {
        if (tid < o) sh[tid] += sh[tid + o];
        __syncthreads();
    }
    if (tid == 0) {
        float md = sh[0] / (float)(K_C * K_C - K_C);
        g_uloss = 0.01f / md;

        float un[K_C], vn[K_C];
        float um = 0.f;
        for (int k = 0; k < K_C; k++) um += g_u[k];
        um /= (float)K_C;
        float uv = 0.f;
        for (int k = 0; k < K_C; k++) { float dd = g_u[k] - um; uv += dd * dd; }
        uv /= (float)(K_C - 1);
        float uis = 1.0f / sqrtf(uv);
        for (int k = 0; k < K_C; k++) un[k] = (g_u[k] - um) * uis;

        float S = g_S;
        float vm = 0.f;
        for (int k = 0; k < K_C; k++) {
            float nc = (g_cnt[k] > 0) ? (float)g_cnt[k] : 1.0f;
            vn[k] = sqrtf(nc) * S;
            vm += vn[k];
        }
        vm /= (float)K_C;
        float vv = 0.f;
        for (int k = 0; k < K_C; k++) { float dd = vn[k] - vm; vv += dd * dd; }
        vv /= (float)(K_C - 1);
        float vis = 1.0f / sqrtf(vv);
        for (int k = 0; k < K_C; k++) vn[k] = (vn[k] - vm) * vis;

        float umin = un[0], vmin = vn[0];
        for (int k = 1; k < K_C; k++) {
            umin = fminf(umin, un[k]);
            vmin = fminf(vmin, vn[k]);
        }
        for (int k = 0; k < K_C; k++) {
            g_f[k] = (un[k] - umin + 0.001f) + (vn[k] - vmin + 0.001f) + 1.0f;
        }
    }
}

__global__ __launch_bounds__(128) void passC(const float* __restrict__ q,
                                             float* __restrict__ klp) {
    __shared__ float fsh[K_C];
    __shared__ float sh[128];
    const int tid = threadIdx.x;
    for (int i = tid; i < K_C; i += 128) fsh[i] = g_f[i];
    __syncthreads();
    const int n = blockIdx.x * 128 + tid;
    float kl = 0.f;
    float ws = 0.f;
    for (int k = 0; k < K_C; k++) {
        float qv = q[(size_t)k * N_PTS + n];
        ws += qv * qv / fsh[k];
    }
    float inv = 1.0f / ws;
    for (int k = 0; k < K_C; k++) {
        float qv = q[(size_t)k * N_PTS + n];
        float p = qv * qv / fsh[k] * inv;
        kl += p * (logf(p) - logf(qv));
    }
    sh[tid] = kl;
    __syncthreads();
    for (int o = 64; o > 0; o >>= 1) {
        if (tid < o) sh[tid] += sh[tid + o];
        __syncthreads();
    }
    if (tid == 0) klp[blockIdx.x] = sh[0];
}

__global__ void finalk(float* __restrict__ out, int out_size) {
    __shared__ float sh[256];
    __shared__ float tot[2];
    const int tid = threadIdx.x;
    float s = 0.f;
    for (int i = tid; i < MSE_PARTIALS; i += 256) s += g_msep[i];
    sh[tid] = s;
    __syncthreads();
    for (int o = 128; o > 0; o >>= 1) {
        if (tid < o) sh[tid] += sh[tid + o];
        __syncthreads();
    }
    if (tid == 0) tot[0] = sh[0];
    __syncthreads();
    s = 0.f;
    for (int i = tid; i < MBLK; i += 256) s += g_klp[i];
    sh[tid] = s;
    __syncthreads();
    for (int o = 128; o > 0; o >>= 1) {
        if (tid < o) sh[tid] += sh[tid + o];
        __syncthreads();
    }
    if (tid == 0) tot[1] = sh[0];
    __syncthreads();
    if (tid == 0) {
        float re_loss = tot[0] / ((float)N_PTS * (float)N_IN_C);
        float kl_loss = tot[1] / ((float)N_PTS * (float)K_C) * 0.01f;
        float loss = kl_loss + re_loss + g_uloss;
        if (out_size > N_PTS) out[N_PTS] = loss;
    }
}

// ---------------- launch ----------------
extern "C" void kernel_launch(void* const* d_in, const int* in_sizes, int n_in,
                              void* d_out, int out_size) {
    const float* x    = (const float*)d_in[0];
    const float* t1   = (const float*)d_in[1];
    const float* clus = (const float*)d_in[2];
    const float* We1  = (const float*)d_in[3];
    const float* be1  = (const float*)d_in[4];
    const float* We2  = (const float*)d_in[5];
    const float* be2  = (const float*)d_in[6];
    const float* We3  = (const float*)d_in[7];
    const float* be3  = (const float*)d_in[8];
    const float* Wz   = (const float*)d_in[9];
    const float* bz   = (const float*)d_in[10];
    const float* Wd1  = (const float*)d_in[11];
    const float* bd1  = (const float*)d_in[12];
    const float* Wd2  = (const float*)d_in[13];
    const float* bd2  = (const float*)d_in[14];
    const float* Wd3  = (const float*)d_in[15];
    const float* bd3  = (const float*)d_in[16];
    const float* Wxb  = (const float*)d_in[17];
    const float* bxb  = (const float*)d_in[18];
    float* out = (float*)d_out;

    float *bufA, *bufB, *zbuf, *qbuf, *scon, *msep, *klp;
    uint32_t *cA0, *cA1, *cA2, *cB0, *cB1, *cB2;
    int *pred;
    cudaGetSymbolAddress((void**)&bufA, g_bufA);
    cudaGetSymbolAddress((void**)&bufB, g_bufB);
    cudaGetSymbolAddress((void**)&cA0, g_cA0);
    cudaGetSymbolAddress((void**)&cA1, g_cA1);
    cudaGetSymbolAddress((void**)&cA2, g_cA2);
    cudaGetSymbolAddress((void**)&cB0, g_cB0);
    cudaGetSymbolAddress((void**)&cB1, g_cB1);
    cudaGetSymbolAddress((void**)&cB2, g_cB2);
    cudaGetSymbolAddress((void**)&zbuf, g_zbuf);
    cudaGetSymbolAddress((void**)&qbuf, g_q);
    cudaGetSymbolAddress((void**)&pred, g_pred);
    cudaGetSymbolAddress((void**)&scon, g_Scon);
    cudaGetSymbolAddress((void**)&msep, g_msep);
    cudaGetSymbolAddress((void**)&klp,  g_klp);

    const int DS3_256 = 2 * 3 * (2048 + 256 * 16) * 4;  // 147456
    const int DS3_128 = 2 * 3 * (2048 + 128 * 16) * 4;  //  98304
    const int DS2_256 = 2 * 2 * (2048 + 256 * 16) * 4;  //  98304
    cudaFuncSetAttribute(mma_bf<3, 0, 256>, cudaFuncAttributeMaxDynamicSharedMemorySize, DS3_256);
    cudaFuncSetAttribute(mma_bf<3, 0, 128>, cudaFuncAttributeMaxDynamicSharedMemorySize, DS3_128);
    cudaFuncSetAttribute(mma_bf<2, 0, 256>, cudaFuncAttributeMaxDynamicSharedMemorySize, DS2_256);
    cudaFuncSetAttribute(mma_bf<2, 1, 256>, cudaFuncAttributeMaxDynamicSharedMemorySize, DS2_256);

    init_kernel<<<1, 128>>>();
    auto nb = [](int elems) { return (elems + 255) / 256; };

    // ---- encoder: 3-way bf16 split, 6 terms ----
    splitA_bf<3><<<nb(N_PTS * 512), 256>>>(x, cA0, cA1, cA2, N_PTS * 512, 10);
    splitB_bf<3><<<nb(512 * E1_C), 256>>>(We1, cB0, cB1, cB2, 512 * E1_C, 9, N_IN_C);
    mma_bf<3, 0, 128><<<dim3(E1_C / 128, MBLK), 512, DS3_128>>>(cA0, cA1, cA2, cB0, cB1, cB2,
        be1, bufA, nullptr, nullptr, N_IN_C, E1_C);

    splitA_bf<3><<<nb(N_PTS * 256), 256>>>(bufA, cA0, cA1, cA2, N_PTS * 256, 9);
    splitB_bf<3><<<nb(256 * E2_C), 256>>>(We2, cB0, cB1, cB2, 256 * E2_C, 9, E1_C);
    mma_bf<3, 0, 128><<<dim3(E2_C / 128, MBLK), 512, DS3_128>>>(cA0, cA1, cA2, cB0, cB1, cB2,
        be2, bufB, nullptr, nullptr, E1_C, E2_C);

    splitA_bf<3><<<nb(N_PTS * 256), 256>>>(bufB, cA0, cA1, cA2, N_PTS * 256, 9);
    splitB_bf<3><<<nb(256 * E3_C), 256>>>(We3, cB0, cB1, cB2, 256 * E3_C, 11, E2_C);
    mma_bf<3, 0, 256><<<dim3(E3_C / 256, MBLK), 512, DS3_256>>>(cA0, cA1, cA2, cB0, cB1, cB2,
        be3, bufA, nullptr, nullptr, E2_C, E3_C);

    // z layer: dedicated scalar fp32 kernel (bit-identical accumulation order)
    gemm_z32<<<N_PTS / 256, 256>>>(bufA, Wz, bz, zbuf, E3_C);

    // ---- decoder: 2-way bf16 split, 3 terms ----
    splitA_bf<2><<<nb(N_PTS * 16), 256>>>(zbuf, cA0, cA1, nullptr, N_PTS * 16, 5);
    splitB_bf<2><<<nb(16 * D1_C), 256>>>(Wd1, cB0, cB1, nullptr, 16 * D1_C, 11, NZ_C);
    mma_bf<2, 0, 256><<<dim3(D1_C / 256, MBLK), 512, DS2_256>>>(cA0, cA1, nullptr, cB0, cB1, nullptr,
        bd1, bufB, nullptr, nullptr, NZ_C, D1_C);

    splitA_bf<2><<<nb(N_PTS * 1024), 256>>>(bufB, cA0, cA1, nullptr, N_PTS * 1024, 11);
    splitB_bf<2><<<nb(1024 * D2_C), 256>>>(Wd2, cB0, cB1, nullptr, 1024 * D2_C, 9, D1_C);
    mma_bf<2, 0, 256><<<dim3(D2_C / 256, MBLK), 512, DS2_256>>>(cA0, cA1, nullptr, cB0, cB1, nullptr,
        bd2, bufA, nullptr, nullptr, D1_C, D2_C);

    splitA_bf<2><<<nb(N_PTS * 256), 256>>>(bufA, cA0, cA1, nullptr, N_PTS * 256, 9);
    splitB_bf<2><<<nb(256 * D3_C), 256>>>(Wd3, cB0, cB1, nullptr, 256 * D3_C, 9, D2_C);
    mma_bf<2, 0, 256><<<dim3(D3_C / 256, MBLK), 512, DS2_256>>>(cA0, cA1, nullptr, cB0, cB1, nullptr,
        bd3, bufB, nullptr, nullptr, D2_C, D3_C);

    splitA_bf<2><<<nb(N_PTS * 256), 256>>>(bufB, cA0, cA1, nullptr, N_PTS * 256, 9);
    splitB_bf<2><<<nb(256 * N_IN_C), 256>>>(Wxb, cB0, cB1, nullptr, 256 * N_IN_C, 10, D3_C);
    mma_bf<2, 1, 256><<<dim3(N_IN_C / 256, MBLK), 512, DS2_256>>>(cA0, cA1, nullptr, cB0, cB1, nullptr,
        bxb, nullptr, x, msep, D3_C, N_IN_C);

    // ---- clustering + losses ----
    passA<<<MBLK, 128>>>(zbuf, t1, clus, qbuf, pred, scon, out, out_size);
    ureduce<<<K_C, 256>>>(qbuf);
    sreduce<<<1, 256>>>(scon);
    passB<<<1, 256>>>(clus);
    passC<<<MBLK, 128>>>(qbuf, klp);
    finalk<<<1, 256>>>(out, out_size);
}